// round 8
// baseline (speedup 1.0000x reference)
#include <cuda_runtime.h>
#include <math.h>

#define SEQ   2048
#define BATCH 2
#define HID   1024
#define NH    16
#define HD    64
#define MTOK  (BATCH*SEQ)   // 4096

// Scratch (allocation-free, per harness rules)
__device__ float g_Q[BATCH*NH*SEQ*HD];   // [b,h,n,d], pre-scaled by 1/8
__device__ float g_K[BATCH*NH*SEQ*HD];   // [b,h,n,d]
__device__ float g_V[BATCH*NH*SEQ*HD];   // [b,h,n,d]
__device__ float g_AO[MTOK*HID];         // [b,n,h*64+d]

// ---------------------------------------------------------------------------
// Kernel 1: QKV GEMM  C[4096,3072] = enc[4096,1024] @ W_attn[1024,3072] + b
// 128x128 tile, BK=16, double-buffered smem with register prefetch.
// 256 threads, 8x8 per thread (4+4 split). Epilogue scatters to Q/K/V.
// ---------------------------------------------------------------------------
__global__ __launch_bounds__(256, 2) void qkv_gemm(const float* __restrict__ A,
                                                   const float* __restrict__ B,
                                                   const float* __restrict__ bias)
{
    const int K = HID, N = 3*HID;
    __shared__ float As[2][16][128];
    __shared__ float Bs[2][16][128];
    const int tid = threadIdx.x;
    const int tx = tid & 15, ty = tid >> 4;
    const int aRow = tid >> 1, aCol = (tid & 1) << 3;   // 8 cols per thread
    const int bRow = tid >> 4, bCol = (tid & 15) << 2;  // + mirror at +64
    const float* Ag = A + (size_t)(blockIdx.y * 128) * K;
    const float* Bg = B + blockIdx.x * 128;

    float acc[8][8];
#pragma unroll
    for (int i = 0; i < 8; i++)
#pragma unroll
        for (int j = 0; j < 8; j++) acc[i][j] = 0.0f;

    // preload tile 0
    float4 pa0 = *(const float4*)(Ag + aRow*K + aCol);
    float4 pa1 = *(const float4*)(Ag + aRow*K + aCol + 4);
    float4 pb0 = *(const float4*)(Bg + (size_t)bRow*N + bCol);
    float4 pb1 = *(const float4*)(Bg + (size_t)bRow*N + bCol + 64);
    As[0][aCol+0][aRow]=pa0.x; As[0][aCol+1][aRow]=pa0.y;
    As[0][aCol+2][aRow]=pa0.z; As[0][aCol+3][aRow]=pa0.w;
    As[0][aCol+4][aRow]=pa1.x; As[0][aCol+5][aRow]=pa1.y;
    As[0][aCol+6][aRow]=pa1.z; As[0][aCol+7][aRow]=pa1.w;
    *(float4*)&Bs[0][bRow][bCol]    = pb0;
    *(float4*)&Bs[0][bRow][bCol+64] = pb1;
    __syncthreads();

    int buf = 0;
    const int NT = K/16;  // 64
    for (int kt = 0; kt < NT; kt++) {
        if (kt < NT-1) {
            const float* Ap = Ag + aRow*K + (kt+1)*16 + aCol;
            pa0 = *(const float4*)Ap;
            pa1 = *(const float4*)(Ap + 4);
            const float* Bp = Bg + (size_t)((kt+1)*16 + bRow)*N + bCol;
            pb0 = *(const float4*)Bp;
            pb1 = *(const float4*)(Bp + 64);
        }
#pragma unroll
        for (int kk = 0; kk < 16; kk++) {
            float4 a0 = *(float4*)&As[buf][kk][ty*4];
            float4 a1 = *(float4*)&As[buf][kk][ty*4 + 64];
            float4 b0 = *(float4*)&Bs[buf][kk][tx*4];
            float4 b1 = *(float4*)&Bs[buf][kk][tx*4 + 64];
            float ra[8] = {a0.x,a0.y,a0.z,a0.w,a1.x,a1.y,a1.z,a1.w};
            float rb[8] = {b0.x,b0.y,b0.z,b0.w,b1.x,b1.y,b1.z,b1.w};
#pragma unroll
            for (int i = 0; i < 8; i++)
#pragma unroll
                for (int j = 0; j < 8; j++)
                    acc[i][j] = fmaf(ra[i], rb[j], acc[i][j]);
        }
        if (kt < NT-1) {
            int nb = buf ^ 1;
            As[nb][aCol+0][aRow]=pa0.x; As[nb][aCol+1][aRow]=pa0.y;
            As[nb][aCol+2][aRow]=pa0.z; As[nb][aCol+3][aRow]=pa0.w;
            As[nb][aCol+4][aRow]=pa1.x; As[nb][aCol+5][aRow]=pa1.y;
            As[nb][aCol+6][aRow]=pa1.z; As[nb][aCol+7][aRow]=pa1.w;
            *(float4*)&Bs[nb][bRow][bCol]    = pb0;
            *(float4*)&Bs[nb][bRow][bCol+64] = pb1;
            __syncthreads();
            buf = nb;
        }
    }

#pragma unroll
    for (int i = 0; i < 8; i++) {
        int m  = blockIdx.y*128 + (i>>2)*64 + ty*4 + (i&3);
        int bb = m >> 11;          // / SEQ
        int n  = m & (SEQ-1);
#pragma unroll
        for (int j = 0; j < 8; j++) {
            int c = blockIdx.x*128 + (j>>2)*64 + tx*4 + (j&3);
            float v = acc[i][j] + bias[c];
            int part = c >> 10;            // 0:Q 1:K 2:V
            int h = (c >> 6) & 15;
            int l = c & 63;
            int dst = ((bb*NH + h)*SEQ + n)*HD + l;
            if (part == 0)      g_Q[dst] = v * 0.125f;   // 1/sqrt(64)
            else if (part == 1) g_K[dst] = v;
            else                g_V[dst] = v;
        }
    }
}

// ---------------------------------------------------------------------------
// Kernel 2: causal flash attention, fp32, transposed smem tiles so inner
// loops are 2x LDS.128 per 16 FFMA (was 8x LDS.32 per 16 FFMA).
// Block = 64 queries of one (b,h). 256 threads as 16x16.
// ---------------------------------------------------------------------------
#define APAD 68   // multiple of 4 -> float4-aligned rows
__global__ __launch_bounds__(256) void attn_kernel(float* __restrict__ AO)
{
    extern __shared__ float sm[];
    float* QsT = sm;                // [d][q]  64x68
    float* KsT = QsT + 64*APAD;     // [d][k]
    float* Vs  = KsT + 64*APAD;     // [k][d]  row-major
    float* PsT = Vs  + 64*APAD;     // [k][q]

    const int qt = blockIdx.x, h = blockIdx.y, b = blockIdx.z;
    const int bh = b*NH + h;
    const float* Qg = g_Q + ((size_t)bh*SEQ + qt*64)*HD;
    const float* Kg = g_K + (size_t)bh*SEQ*HD;
    const float* Vg = g_V + (size_t)bh*SEQ*HD;

    const int tid = threadIdx.x;
    const int tk = tid & 15, tq = tid >> 4;
    const int q0 = tq*4, k0 = tk*4, d0 = tk*4;

    // Load Q tile transposed: QsT[d][q]
#pragma unroll
    for (int t = 0; t < 4; t++) {
        int idx = t*256 + tid;
        int r = idx >> 4, c4 = (idx & 15) << 2;
        float4 v = *(const float4*)(Qg + r*HD + c4);
        QsT[(c4+0)*APAD + r] = v.x; QsT[(c4+1)*APAD + r] = v.y;
        QsT[(c4+2)*APAD + r] = v.z; QsT[(c4+3)*APAD + r] = v.w;
    }

    float mrow[4], lrow[4], O[4][4];
#pragma unroll
    for (int i = 0; i < 4; i++) {
        mrow[i] = -1e30f; lrow[i] = 0.0f;
#pragma unroll
        for (int j = 0; j < 4; j++) O[i][j] = 0.0f;
    }
    __syncthreads();

    for (int kt = 0; kt <= qt; kt++) {
        const float* Kt = Kg + (size_t)kt*64*HD;
        const float* Vt = Vg + (size_t)kt*64*HD;
#pragma unroll
        for (int t = 0; t < 4; t++) {
            int idx = t*256 + tid;
            int r = idx >> 4, c4 = (idx & 15) << 2;
            float4 kv = *(const float4*)(Kt + r*HD + c4);
            KsT[(c4+0)*APAD + r] = kv.x; KsT[(c4+1)*APAD + r] = kv.y;
            KsT[(c4+2)*APAD + r] = kv.z; KsT[(c4+3)*APAD + r] = kv.w;
            float4 vv = *(const float4*)(Vt + r*HD + c4);
            *(float4*)&Vs[r*APAD + c4] = vv;
        }
        __syncthreads();

        // S = Q . K^T   (Q pre-scaled by 1/8)
        float s[4][4];
#pragma unroll
        for (int i = 0; i < 4; i++)
#pragma unroll
            for (int j = 0; j < 4; j++) s[i][j] = 0.0f;
#pragma unroll 8
        for (int d = 0; d < HD; d++) {
            float4 qv = *(float4*)&QsT[d*APAD + q0];
            float4 kv = *(float4*)&KsT[d*APAD + k0];
            float qr[4] = {qv.x, qv.y, qv.z, qv.w};
            float kr[4] = {kv.x, kv.y, kv.z, kv.w};
#pragma unroll
            for (int i = 0; i < 4; i++)
#pragma unroll
                for (int j = 0; j < 4; j++)
                    s[i][j] = fmaf(qr[i], kr[j], s[i][j]);
        }

        // Causal mask on diagonal tile
        if (kt == qt) {
#pragma unroll
            for (int i = 0; i < 4; i++)
#pragma unroll
                for (int j = 0; j < 4; j++)
                    if (k0 + j > q0 + i) s[i][j] = -1e30f;
        }

        // Online softmax (16-lane key-group reductions)
#pragma unroll
        for (int i = 0; i < 4; i++) {
            float v = fmaxf(fmaxf(s[i][0], s[i][1]), fmaxf(s[i][2], s[i][3]));
#pragma unroll
            for (int off = 8; off >= 1; off >>= 1)
                v = fmaxf(v, __shfl_xor_sync(0xffffffffu, v, off, 16));
            float mn = fmaxf(mrow[i], v);
            float alpha = __expf(mrow[i] - mn);
#pragma unroll
            for (int j = 0; j < 4; j++) s[i][j] = __expf(s[i][j] - mn);
            float r = s[i][0] + s[i][1] + s[i][2] + s[i][3];
#pragma unroll
            for (int off = 8; off >= 1; off >>= 1)
                r += __shfl_xor_sync(0xffffffffu, r, off, 16);
            lrow[i] = lrow[i]*alpha + r;
            mrow[i] = mn;
#pragma unroll
            for (int j = 0; j < 4; j++) O[i][j] *= alpha;
        }

        // Stage P transposed: PsT[k][q]
#pragma unroll
        for (int j = 0; j < 4; j++)
#pragma unroll
            for (int i = 0; i < 4; i++)
                PsT[(k0+j)*APAD + q0 + i] = s[i][j];
        __syncthreads();

        // O += P . V
#pragma unroll 8
        for (int k = 0; k < 64; k++) {
            float4 pv = *(float4*)&PsT[k*APAD + q0];
            float4 vv = *(float4*)&Vs[k*APAD + d0];
            float pr[4] = {pv.x, pv.y, pv.z, pv.w};
            float vr[4] = {vv.x, vv.y, vv.z, vv.w};
#pragma unroll
            for (int i = 0; i < 4; i++)
#pragma unroll
                for (int j = 0; j < 4; j++)
                    O[i][j] = fmaf(pr[i], vr[j], O[i][j]);
        }
        __syncthreads();
    }

    // Normalize + write [b, n, h*64+d]
#pragma unroll
    for (int i = 0; i < 4; i++) {
        float inv = 1.0f / lrow[i];
        int qglob = qt*64 + q0 + i;
        float* dst = AO + ((size_t)(b*SEQ + qglob))*HID + h*HD + d0;
#pragma unroll
        for (int j = 0; j < 4; j++) dst[j] = O[i][j] * inv;
    }
}

// ---------------------------------------------------------------------------
// Kernel 3: output projection  out[4096,1024] = AO @ W_out + b_out
// Same double-buffered BK=16 scheme.
// ---------------------------------------------------------------------------
__global__ __launch_bounds__(256, 2) void out_gemm(const float* __restrict__ A,
                                                   const float* __restrict__ B,
                                                   const float* __restrict__ bias,
                                                   float* __restrict__ C)
{
    const int K = HID, N = HID;
    __shared__ float As[2][16][128];
    __shared__ float Bs[2][16][128];
    const int tid = threadIdx.x;
    const int tx = tid & 15, ty = tid >> 4;
    const int aRow = tid >> 1, aCol = (tid & 1) << 3;
    const int bRow = tid >> 4, bCol = (tid & 15) << 2;
    const float* Ag = A + (size_t)(blockIdx.y * 128) * K;
    const float* Bg = B + blockIdx.x * 128;

    float acc[8][8];
#pragma unroll
    for (int i = 0; i < 8; i++)
#pragma unroll
        for (int j = 0; j < 8; j++) acc[i][j] = 0.0f;

    float4 pa0 = *(const float4*)(Ag + aRow*K + aCol);
    float4 pa1 = *(const float4*)(Ag + aRow*K + aCol + 4);
    float4 pb0 = *(const float4*)(Bg + (size_t)bRow*N + bCol);
    float4 pb1 = *(const float4*)(Bg + (size_t)bRow*N + bCol + 64);
    As[0][aCol+0][aRow]=pa0.x; As[0][aCol+1][aRow]=pa0.y;
    As[0][aCol+2][aRow]=pa0.z; As[0][aCol+3][aRow]=pa0.w;
    As[0][aCol+4][aRow]=pa1.x; As[0][aCol+5][aRow]=pa1.y;
    As[0][aCol+6][aRow]=pa1.z; As[0][aCol+7][aRow]=pa1.w;
    *(float4*)&Bs[0][bRow][bCol]    = pb0;
    *(float4*)&Bs[0][bRow][bCol+64] = pb1;
    __syncthreads();

    int buf = 0;
    const int NT = K/16;
    for (int kt = 0; kt < NT; kt++) {
        if (kt < NT-1) {
            const float* Ap = Ag + aRow*K + (kt+1)*16 + aCol;
            pa0 = *(const float4*)Ap;
            pa1 = *(const float4*)(Ap + 4);
            const float* Bp = Bg + (size_t)((kt+1)*16 + bRow)*N + bCol;
            pb0 = *(const float4*)Bp;
            pb1 = *(const float4*)(Bp + 64);
        }
#pragma unroll
        for (int kk = 0; kk < 16; kk++) {
            float4 a0 = *(float4*)&As[buf][kk][ty*4];
            float4 a1 = *(float4*)&As[buf][kk][ty*4 + 64];
            float4 b0 = *(float4*)&Bs[buf][kk][tx*4];
            float4 b1 = *(float4*)&Bs[buf][kk][tx*4 + 64];
            float ra[8] = {a0.x,a0.y,a0.z,a0.w,a1.x,a1.y,a1.z,a1.w};
            float rb[8] = {b0.x,b0.y,b0.z,b0.w,b1.x,b1.y,b1.z,b1.w};
#pragma unroll
            for (int i = 0; i < 8; i++)
#pragma unroll
                for (int j = 0; j < 8; j++)
                    acc[i][j] = fmaf(ra[i], rb[j], acc[i][j]);
        }
        if (kt < NT-1) {
            int nb = buf ^ 1;
            As[nb][aCol+0][aRow]=pa0.x; As[nb][aCol+1][aRow]=pa0.y;
            As[nb][aCol+2][aRow]=pa0.z; As[nb][aCol+3][aRow]=pa0.w;
            As[nb][aCol+4][aRow]=pa1.x; As[nb][aCol+5][aRow]=pa1.y;
            As[nb][aCol+6][aRow]=pa1.z; As[nb][aCol+7][aRow]=pa1.w;
            *(float4*)&Bs[nb][bRow][bCol]    = pb0;
            *(float4*)&Bs[nb][bRow][bCol+64] = pb1;
            __syncthreads();
            buf = nb;
        }
    }

#pragma unroll
    for (int i = 0; i < 8; i++) {
        int m = blockIdx.y*128 + (i>>2)*64 + ty*4 + (i&3);
#pragma unroll
        for (int j = 0; j < 8; j++) {
            int c = blockIdx.x*128 + (j>>2)*64 + tx*4 + (j&3);
            C[(size_t)m*N + c] = acc[i][j] + bias[c];
        }
    }
}

// ---------------------------------------------------------------------------
extern "C" void kernel_launch(void* const* d_in, const int* in_sizes, int n_in,
                              void* d_out, int out_size)
{
    const float* enc    = (const float*)d_in[0];  // [2,2048,1024]
    const float* W_attn = (const float*)d_in[1];  // [1024,3072]
    const float* b_attn = (const float*)d_in[2];  // [3072]
    const float* W_out  = (const float*)d_in[3];  // [1024,1024]
    const float* b_out  = (const float*)d_in[4];  // [1024]
    float* out = (float*)d_out;                   // [2,2048,1024]

    float* d_AO = nullptr;
    cudaGetSymbolAddress((void**)&d_AO, g_AO);

    // 1) QKV projection + head-major scatter
    {
        dim3 grid(3*HID/128, MTOK/128);  // 24 x 32
        qkv_gemm<<<grid, 256>>>(enc, W_attn, b_attn);
    }

    // 2) causal attention
    {
        size_t smem = (size_t)4 * 64 * APAD * sizeof(float);  // 69632 B
        cudaFuncSetAttribute(attn_kernel,
                             cudaFuncAttributeMaxDynamicSharedMemorySize,
                             (int)smem);
        dim3 grid(SEQ/64, NH, BATCH);    // 32 x 16 x 2
        attn_kernel<<<grid, 256, smem>>>(d_AO);
    }

    // 3) output projection
    {
        dim3 grid(HID/128, MTOK/128);    // 8 x 32
        out_gemm<<<grid, 256>>>(d_AO, W_out, b_out, out);
    }
}

// round 9
// speedup vs baseline: 1.0135x; 1.0135x over previous
#include <cuda_runtime.h>
#include <math.h>

#define SEQ   2048
#define BATCH 2
#define HID   1024
#define NH    16
#define HD    64
#define MTOK  (BATCH*SEQ)   // 4096

// Scratch (allocation-free, per harness rules)
__device__ float g_Q[BATCH*NH*SEQ*HD];   // [b,h,n,d], pre-scaled by 1/8
__device__ float g_K[BATCH*NH*SEQ*HD];   // [b,h,n,d]
__device__ float g_V[BATCH*NH*SEQ*HD];   // [b,h,n,d]
__device__ float g_AO[MTOK*HID];         // [b,n,h*64+d]

// ---------------------------------------------------------------------------
// Kernel 1: QKV GEMM  C[4096,3072] = enc[4096,1024] @ W_attn[1024,3072] + b
// 128x128 tile, BK=16, double-buffered smem with register prefetch.
// 256 threads, 8x8 per thread (4+4 split). Epilogue scatters to Q/K/V.
// ---------------------------------------------------------------------------
__global__ __launch_bounds__(256, 2) void qkv_gemm(const float* __restrict__ A,
                                                   const float* __restrict__ B,
                                                   const float* __restrict__ bias)
{
    const int K = HID, N = 3*HID;
    __shared__ float As[2][16][128];
    __shared__ float Bs[2][16][128];
    const int tid = threadIdx.x;
    const int tx = tid & 15, ty = tid >> 4;
    const int aRow = tid >> 1, aCol = (tid & 1) << 3;   // 8 cols per thread
    const int bRow = tid >> 4, bCol = (tid & 15) << 2;  // + mirror at +64
    const float* Ag = A + (size_t)(blockIdx.y * 128) * K;
    const float* Bg = B + blockIdx.x * 128;

    float acc[8][8];
#pragma unroll
    for (int i = 0; i < 8; i++)
#pragma unroll
        for (int j = 0; j < 8; j++) acc[i][j] = 0.0f;

    // preload tile 0
    float4 pa0 = *(const float4*)(Ag + aRow*K + aCol);
    float4 pa1 = *(const float4*)(Ag + aRow*K + aCol + 4);
    float4 pb0 = *(const float4*)(Bg + (size_t)bRow*N + bCol);
    float4 pb1 = *(const float4*)(Bg + (size_t)bRow*N + bCol + 64);
    As[0][aCol+0][aRow]=pa0.x; As[0][aCol+1][aRow]=pa0.y;
    As[0][aCol+2][aRow]=pa0.z; As[0][aCol+3][aRow]=pa0.w;
    As[0][aCol+4][aRow]=pa1.x; As[0][aCol+5][aRow]=pa1.y;
    As[0][aCol+6][aRow]=pa1.z; As[0][aCol+7][aRow]=pa1.w;
    *(float4*)&Bs[0][bRow][bCol]    = pb0;
    *(float4*)&Bs[0][bRow][bCol+64] = pb1;
    __syncthreads();

    int buf = 0;
    const int NT = K/16;  // 64
    for (int kt = 0; kt < NT; kt++) {
        if (kt < NT-1) {
            const float* Ap = Ag + aRow*K + (kt+1)*16 + aCol;
            pa0 = *(const float4*)Ap;
            pa1 = *(const float4*)(Ap + 4);
            const float* Bp = Bg + (size_t)((kt+1)*16 + bRow)*N + bCol;
            pb0 = *(const float4*)Bp;
            pb1 = *(const float4*)(Bp + 64);
        }
#pragma unroll
        for (int kk = 0; kk < 16; kk++) {
            float4 a0 = *(float4*)&As[buf][kk][ty*4];
            float4 a1 = *(float4*)&As[buf][kk][ty*4 + 64];
            float4 b0 = *(float4*)&Bs[buf][kk][tx*4];
            float4 b1 = *(float4*)&Bs[buf][kk][tx*4 + 64];
            float ra[8] = {a0.x,a0.y,a0.z,a0.w,a1.x,a1.y,a1.z,a1.w};
            float rb[8] = {b0.x,b0.y,b0.z,b0.w,b1.x,b1.y,b1.z,b1.w};
#pragma unroll
            for (int i = 0; i < 8; i++)
#pragma unroll
                for (int j = 0; j < 8; j++)
                    acc[i][j] = fmaf(ra[i], rb[j], acc[i][j]);
        }
        if (kt < NT-1) {
            int nb = buf ^ 1;
            As[nb][aCol+0][aRow]=pa0.x; As[nb][aCol+1][aRow]=pa0.y;
            As[nb][aCol+2][aRow]=pa0.z; As[nb][aCol+3][aRow]=pa0.w;
            As[nb][aCol+4][aRow]=pa1.x; As[nb][aCol+5][aRow]=pa1.y;
            As[nb][aCol+6][aRow]=pa1.z; As[nb][aCol+7][aRow]=pa1.w;
            *(float4*)&Bs[nb][bRow][bCol]    = pb0;
            *(float4*)&Bs[nb][bRow][bCol+64] = pb1;
            __syncthreads();
            buf = nb;
        }
    }

#pragma unroll
    for (int i = 0; i < 8; i++) {
        int m  = blockIdx.y*128 + (i>>2)*64 + ty*4 + (i&3);
        int bb = m >> 11;          // / SEQ
        int n  = m & (SEQ-1);
#pragma unroll
        for (int j = 0; j < 8; j++) {
            int c = blockIdx.x*128 + (j>>2)*64 + tx*4 + (j&3);
            float v = acc[i][j] + bias[c];
            int part = c >> 10;            // 0:Q 1:K 2:V
            int h = (c >> 6) & 15;
            int l = c & 63;
            int dst = ((bb*NH + h)*SEQ + n)*HD + l;
            if (part == 0)      g_Q[dst] = v * 0.125f;   // 1/sqrt(64)
            else if (part == 1) g_K[dst] = v;
            else                g_V[dst] = v;
        }
    }
}

// ---------------------------------------------------------------------------
// Kernel 2: causal flash attention, fp32, transposed smem tiles so inner
// loops are 2x LDS.128 per 16 FFMA (was 8x LDS.32 per 16 FFMA).
// Block = 64 queries of one (b,h). 256 threads as 16x16.
// ---------------------------------------------------------------------------
#define APAD 68   // multiple of 4 -> float4-aligned rows
__global__ __launch_bounds__(256) void attn_kernel(float* __restrict__ AO)
{
    extern __shared__ float sm[];
    float* QsT = sm;                // [d][q]  64x68
    float* KsT = QsT + 64*APAD;     // [d][k]
    float* Vs  = KsT + 64*APAD;     // [k][d]  row-major
    float* PsT = Vs  + 64*APAD;     // [k][q]

    const int qt = blockIdx.x, h = blockIdx.y, b = blockIdx.z;
    const int bh = b*NH + h;
    const float* Qg = g_Q + ((size_t)bh*SEQ + qt*64)*HD;
    const float* Kg = g_K + (size_t)bh*SEQ*HD;
    const float* Vg = g_V + (size_t)bh*SEQ*HD;

    const int tid = threadIdx.x;
    const int tk = tid & 15, tq = tid >> 4;
    const int q0 = tq*4, k0 = tk*4, d0 = tk*4;

    // Load Q tile transposed: QsT[d][q]
#pragma unroll
    for (int t = 0; t < 4; t++) {
        int idx = t*256 + tid;
        int r = idx >> 4, c4 = (idx & 15) << 2;
        float4 v = *(const float4*)(Qg + r*HD + c4);
        QsT[(c4+0)*APAD + r] = v.x; QsT[(c4+1)*APAD + r] = v.y;
        QsT[(c4+2)*APAD + r] = v.z; QsT[(c4+3)*APAD + r] = v.w;
    }

    float mrow[4], lrow[4], O[4][4];
#pragma unroll
    for (int i = 0; i < 4; i++) {
        mrow[i] = -1e30f; lrow[i] = 0.0f;
#pragma unroll
        for (int j = 0; j < 4; j++) O[i][j] = 0.0f;
    }
    __syncthreads();

    for (int kt = 0; kt <= qt; kt++) {
        const float* Kt = Kg + (size_t)kt*64*HD;
        const float* Vt = Vg + (size_t)kt*64*HD;
#pragma unroll
        for (int t = 0; t < 4; t++) {
            int idx = t*256 + tid;
            int r = idx >> 4, c4 = (idx & 15) << 2;
            float4 kv = *(const float4*)(Kt + r*HD + c4);
            KsT[(c4+0)*APAD + r] = kv.x; KsT[(c4+1)*APAD + r] = kv.y;
            KsT[(c4+2)*APAD + r] = kv.z; KsT[(c4+3)*APAD + r] = kv.w;
            float4 vv = *(const float4*)(Vt + r*HD + c4);
            *(float4*)&Vs[r*APAD + c4] = vv;
        }
        __syncthreads();

        // S = Q . K^T   (Q pre-scaled by 1/8)
        float s[4][4];
#pragma unroll
        for (int i = 0; i < 4; i++)
#pragma unroll
            for (int j = 0; j < 4; j++) s[i][j] = 0.0f;
#pragma unroll 8
        for (int d = 0; d < HD; d++) {
            float4 qv = *(float4*)&QsT[d*APAD + q0];
            float4 kv = *(float4*)&KsT[d*APAD + k0];
            float qr[4] = {qv.x, qv.y, qv.z, qv.w};
            float kr[4] = {kv.x, kv.y, kv.z, kv.w};
#pragma unroll
            for (int i = 0; i < 4; i++)
#pragma unroll
                for (int j = 0; j < 4; j++)
                    s[i][j] = fmaf(qr[i], kr[j], s[i][j]);
        }

        // Causal mask on diagonal tile
        if (kt == qt) {
#pragma unroll
            for (int i = 0; i < 4; i++)
#pragma unroll
                for (int j = 0; j < 4; j++)
                    if (k0 + j > q0 + i) s[i][j] = -1e30f;
        }

        // Online softmax (16-lane key-group reductions)
#pragma unroll
        for (int i = 0; i < 4; i++) {
            float v = fmaxf(fmaxf(s[i][0], s[i][1]), fmaxf(s[i][2], s[i][3]));
#pragma unroll
            for (int off = 8; off >= 1; off >>= 1)
                v = fmaxf(v, __shfl_xor_sync(0xffffffffu, v, off, 16));
            float mn = fmaxf(mrow[i], v);
            float alpha = __expf(mrow[i] - mn);
#pragma unroll
            for (int j = 0; j < 4; j++) s[i][j] = __expf(s[i][j] - mn);
            float r = s[i][0] + s[i][1] + s[i][2] + s[i][3];
#pragma unroll
            for (int off = 8; off >= 1; off >>= 1)
                r += __shfl_xor_sync(0xffffffffu, r, off, 16);
            lrow[i] = lrow[i]*alpha + r;
            mrow[i] = mn;
#pragma unroll
            for (int j = 0; j < 4; j++) O[i][j] *= alpha;
        }

        // Stage P transposed: PsT[k][q]
#pragma unroll
        for (int j = 0; j < 4; j++)
#pragma unroll
            for (int i = 0; i < 4; i++)
                PsT[(k0+j)*APAD + q0 + i] = s[i][j];
        __syncthreads();

        // O += P . V
#pragma unroll 8
        for (int k = 0; k < 64; k++) {
            float4 pv = *(float4*)&PsT[k*APAD + q0];
            float4 vv = *(float4*)&Vs[k*APAD + d0];
            float pr[4] = {pv.x, pv.y, pv.z, pv.w};
            float vr[4] = {vv.x, vv.y, vv.z, vv.w};
#pragma unroll
            for (int i = 0; i < 4; i++)
#pragma unroll
                for (int j = 0; j < 4; j++)
                    O[i][j] = fmaf(pr[i], vr[j], O[i][j]);
        }
        __syncthreads();
    }

    // Normalize + write [b, n, h*64+d]
#pragma unroll
    for (int i = 0; i < 4; i++) {
        float inv = 1.0f / lrow[i];
        int qglob = qt*64 + q0 + i;
        float* dst = AO + ((size_t)(b*SEQ + qglob))*HID + h*HD + d0;
#pragma unroll
        for (int j = 0; j < 4; j++) dst[j] = O[i][j] * inv;
    }
}

// ---------------------------------------------------------------------------
// Kernel 3: output projection  out[4096,1024] = AO @ W_out + b_out
// Same double-buffered BK=16 scheme.
// ---------------------------------------------------------------------------
__global__ __launch_bounds__(256, 2) void out_gemm(const float* __restrict__ A,
                                                   const float* __restrict__ B,
                                                   const float* __restrict__ bias,
                                                   float* __restrict__ C)
{
    const int K = HID, N = HID;
    __shared__ float As[2][16][128];
    __shared__ float Bs[2][16][128];
    const int tid = threadIdx.x;
    const int tx = tid & 15, ty = tid >> 4;
    const int aRow = tid >> 1, aCol = (tid & 1) << 3;
    const int bRow = tid >> 4, bCol = (tid & 15) << 2;
    const float* Ag = A + (size_t)(blockIdx.y * 128) * K;
    const float* Bg = B + blockIdx.x * 128;

    float acc[8][8];
#pragma unroll
    for (int i = 0; i < 8; i++)
#pragma unroll
        for (int j = 0; j < 8; j++) acc[i][j] = 0.0f;

    float4 pa0 = *(const float4*)(Ag + aRow*K + aCol);
    float4 pa1 = *(const float4*)(Ag + aRow*K + aCol + 4);
    float4 pb0 = *(const float4*)(Bg + (size_t)bRow*N + bCol);
    float4 pb1 = *(const float4*)(Bg + (size_t)bRow*N + bCol + 64);
    As[0][aCol+0][aRow]=pa0.x; As[0][aCol+1][aRow]=pa0.y;
    As[0][aCol+2][aRow]=pa0.z; As[0][aCol+3][aRow]=pa0.w;
    As[0][aCol+4][aRow]=pa1.x; As[0][aCol+5][aRow]=pa1.y;
    As[0][aCol+6][aRow]=pa1.z; As[0][aCol+7][aRow]=pa1.w;
    *(float4*)&Bs[0][bRow][bCol]    = pb0;
    *(float4*)&Bs[0][bRow][bCol+64] = pb1;
    __syncthreads();

    int buf = 0;
    const int NT = K/16;
    for (int kt = 0; kt < NT; kt++) {
        if (kt < NT-1) {
            const float* Ap = Ag + aRow*K + (kt+1)*16 + aCol;
            pa0 = *(const float4*)Ap;
            pa1 = *(const float4*)(Ap + 4);
            const float* Bp = Bg + (size_t)((kt+1)*16 + bRow)*N + bCol;
            pb0 = *(const float4*)Bp;
            pb1 = *(const float4*)(Bp + 64);
        }
#pragma unroll
        for (int kk = 0; kk < 16; kk++) {
            float4 a0 = *(float4*)&As[buf][kk][ty*4];
            float4 a1 = *(float4*)&As[buf][kk][ty*4 + 64];
            float4 b0 = *(float4*)&Bs[buf][kk][tx*4];
            float4 b1 = *(float4*)&Bs[buf][kk][tx*4 + 64];
            float ra[8] = {a0.x,a0.y,a0.z,a0.w,a1.x,a1.y,a1.z,a1.w};
            float rb[8] = {b0.x,b0.y,b0.z,b0.w,b1.x,b1.y,b1.z,b1.w};
#pragma unroll
            for (int i = 0; i < 8; i++)
#pragma unroll
                for (int j = 0; j < 8; j++)
                    acc[i][j] = fmaf(ra[i], rb[j], acc[i][j]);
        }
        if (kt < NT-1) {
            int nb = buf ^ 1;
            As[nb][aCol+0][aRow]=pa0.x; As[nb][aCol+1][aRow]=pa0.y;
            As[nb][aCol+2][aRow]=pa0.z; As[nb][aCol+3][aRow]=pa0.w;
            As[nb][aCol+4][aRow]=pa1.x; As[nb][aCol+5][aRow]=pa1.y;
            As[nb][aCol+6][aRow]=pa1.z; As[nb][aCol+7][aRow]=pa1.w;
            *(float4*)&Bs[nb][bRow][bCol]    = pb0;
            *(float4*)&Bs[nb][bRow][bCol+64] = pb1;
            __syncthreads();
            buf = nb;
        }
    }

#pragma unroll
    for (int i = 0; i < 8; i++) {
        int m = blockIdx.y*128 + (i>>2)*64 + ty*4 + (i&3);
#pragma unroll
        for (int j = 0; j < 8; j++) {
            int c = blockIdx.x*128 + (j>>2)*64 + tx*4 + (j&3);
            C[(size_t)m*N + c] = acc[i][j] + bias[c];
        }
    }
}

// ---------------------------------------------------------------------------
extern "C" void kernel_launch(void* const* d_in, const int* in_sizes, int n_in,
                              void* d_out, int out_size)
{
    const float* enc    = (const float*)d_in[0];  // [2,2048,1024]
    const float* W_attn = (const float*)d_in[1];  // [1024,3072]
    const float* b_attn = (const float*)d_in[2];  // [3072]
    const float* W_out  = (const float*)d_in[3];  // [1024,1024]
    const float* b_out  = (const float*)d_in[4];  // [1024]
    float* out = (float*)d_out;                   // [2,2048,1024]

    float* d_AO = nullptr;
    cudaGetSymbolAddress((void**)&d_AO, g_AO);

    // 1) QKV projection + head-major scatter
    {
        dim3 grid(3*HID/128, MTOK/128);  // 24 x 32
        qkv_gemm<<<grid, 256>>>(enc, W_attn, b_attn);
    }

    // 2) causal attention
    {
        size_t smem = (size_t)4 * 64 * APAD * sizeof(float);  // 69632 B
        cudaFuncSetAttribute(attn_kernel,
                             cudaFuncAttributeMaxDynamicSharedMemorySize,
                             (int)smem);
        dim3 grid(SEQ/64, NH, BATCH);    // 32 x 16 x 2
        attn_kernel<<<grid, 256, smem>>>(d_AO);
    }

    // 3) output projection
    {
        dim3 grid(HID/128, MTOK/128);    // 8 x 32
        out_gemm<<<grid, 256>>>(d_AO, W_out, b_out, out);
    }
}

// round 13
// speedup vs baseline: 1.3136x; 1.2961x over previous
#include <cuda_runtime.h>
#include <cuda_bf16.h>
#include <stdint.h>
#include <math.h>

#define SEQ   2048
#define BATCH 2
#define HID   1024
#define NH    16
#define HD    64
#define MTOK  (BATCH*SEQ)   // 4096

// ---------------- scratch (allocation-free) ----------------
__device__ float g_Q[BATCH*NH*SEQ*HD];   // [b,h,n,d], pre-scaled by 1/8
__device__ float g_K[BATCH*NH*SEQ*HD];
__device__ float g_V[BATCH*NH*SEQ*HD];
__device__ float g_AO[MTOK*HID];
__device__ __nv_bfloat16 g_Ah[MTOK*HID],    g_Al[MTOK*HID];      // enc split
__device__ __nv_bfloat16 g_WqTh[3*HID*HID], g_WqTl[3*HID*HID];   // W_attn^T split [3072][1024]
__device__ __nv_bfloat16 g_WoTh[HID*HID],   g_WoTl[HID*HID];     // W_out^T split [1024][1024]
__device__ __nv_bfloat16 g_AOh[MTOK*HID],   g_AOl[MTOK*HID];     // attn out split

__device__ __forceinline__ uint32_t smem_u32(const void* p) {
    uint32_t a;
    asm("{ .reg .u64 t; cvta.to.shared.u64 t, %1; cvt.u32.u64 %0, t; }" : "=r"(a) : "l"(p));
    return a;
}

__device__ __forceinline__ void mma_bf16(float* d,
                                         uint32_t a0, uint32_t a1, uint32_t a2, uint32_t a3,
                                         uint32_t b0, uint32_t b1) {
    asm volatile("mma.sync.aligned.m16n8k16.row.col.f32.bf16.bf16.f32 "
                 "{%0,%1,%2,%3}, {%4,%5,%6,%7}, {%8,%9}, {%0,%1,%2,%3};"
                 : "+f"(d[0]), "+f"(d[1]), "+f"(d[2]), "+f"(d[3])
                 : "r"(a0), "r"(a1), "r"(a2), "r"(a3), "r"(b0), "r"(b1));
}

// ---------------- split / transpose-split ----------------
__global__ void split_kernel(const float4* __restrict__ src,
                             __nv_bfloat16* __restrict__ h,
                             __nv_bfloat16* __restrict__ l, int n4)
{
    int i = blockIdx.x * blockDim.x + threadIdx.x;
    if (i >= n4) return;
    float4 v = src[i];
    float a[4] = {v.x, v.y, v.z, v.w};
#pragma unroll
    for (int j = 0; j < 4; j++) {
        __nv_bfloat16 hi = __float2bfloat16(a[j]);
        h[4*i + j] = hi;
        l[4*i + j] = __float2bfloat16(a[j] - __bfloat162float(hi));
    }
}

__global__ void transpose_split(const float* __restrict__ W,
                                __nv_bfloat16* __restrict__ Th,
                                __nv_bfloat16* __restrict__ Tl, int K, int N)
{
    __shared__ float t[32][33];
    int bn = blockIdx.x * 32, bk = blockIdx.y * 32;
    int tx = threadIdx.x, ty = threadIdx.y;
#pragma unroll
    for (int j = 0; j < 32; j += 8)
        t[ty + j][tx] = W[(size_t)(bk + ty + j) * N + bn + tx];
    __syncthreads();
#pragma unroll
    for (int j = 0; j < 32; j += 8) {
        float v = t[tx][ty + j];
        __nv_bfloat16 hi = __float2bfloat16(v);
        size_t o = (size_t)(bn + ty + j) * K + bk + tx;
        Th[o] = hi;
        Tl[o] = __float2bfloat16(v - __bfloat162float(hi));
    }
}

// ---------------------------------------------------------------------------
// Split-bf16 HMMA GEMM: C[4096, N] = A @ B^T + bias  (3-product: hh+hl+lh)
// A hi/lo row-major [4096][1024]; B^T hi/lo row-major [N][1024].
// CTA tile 128x128, BK=32, cp.async double buffer, 8 warps (2x4), each 64x32.
// MODE 0: qkv scatter epilogue. MODE 1: plain C (+bias).
// ---------------------------------------------------------------------------
#define PB 40              // smem row pitch in bf16 (80 B): conflict-free + 16B-aligned
#define TILE_ELEMS (128*PB)          // 5120 bf16 = 10240 B per tile
#define BUF_ELEMS  (4*TILE_ELEMS)    // Ah,Al,Bh,Bl

template<int MODE>
__global__ __launch_bounds__(256, 1) void gemm_mma(
    const __nv_bfloat16* __restrict__ Ah, const __nv_bfloat16* __restrict__ Al,
    const __nv_bfloat16* __restrict__ Bh, const __nv_bfloat16* __restrict__ Bl,
    const float* __restrict__ bias, float* __restrict__ C)
{
    extern __shared__ __nv_bfloat16 sm[];
    const int tid = threadIdx.x, lane = tid & 31, warp = tid >> 5;
    const int wm = warp >> 2, wn = warp & 3;
    const int rowM = blockIdx.y * 128, rowN = blockIdx.x * 128;
    const uint32_t sbase = smem_u32(sm);

    float acc[4][4][4];
#pragma unroll
    for (int a = 0; a < 4; a++)
#pragma unroll
        for (int b = 0; b < 4; b++)
#pragma unroll
            for (int c = 0; c < 4; c++) acc[a][b][c] = 0.0f;

    const __nv_bfloat16* gsrc[4] = {Ah, Al, Bh, Bl};
    const int rb[4] = {rowM, rowM, rowN, rowN};

    auto issue = [&](int ch, int buf) {
#pragma unroll
        for (int t4 = 0; t4 < 4; t4++) {
#pragma unroll
            for (int t = 0; t < 2; t++) {
                int idx = t * 256 + tid;
                int r = idx >> 2, cq = idx & 3;           // 4x 16B chunks per 32-col row
                const __nv_bfloat16* g = gsrc[t4] + (size_t)(rb[t4] + r) * HID + ch * 32 + cq * 8;
                uint32_t s = sbase + (uint32_t)(buf * BUF_ELEMS + t4 * TILE_ELEMS) * 2u
                                   + (uint32_t)(r * (PB * 2) + cq * 16);
                asm volatile("cp.async.cg.shared.global [%0], [%1], 16;\n"
                             :: "r"(s), "l"(g));
            }
        }
        asm volatile("cp.async.commit_group;\n" ::: "memory");
    };

    issue(0, 0);

    const int NC = HID / 32;   // 32 chunks
    for (int ch = 0; ch < NC; ch++) {
        if (ch + 1 < NC) {
            issue(ch + 1, (ch + 1) & 1);
            asm volatile("cp.async.wait_group 1;\n" ::: "memory");
        } else {
            asm volatile("cp.async.wait_group 0;\n" ::: "memory");
        }
        __syncthreads();

        const __nv_bfloat16* base = sm + (ch & 1) * BUF_ELEMS;
        const __nv_bfloat16* Ahs = base;
        const __nv_bfloat16* Als = base + TILE_ELEMS;
        const __nv_bfloat16* Bhs = base + 2 * TILE_ELEMS;
        const __nv_bfloat16* Bls = base + 3 * TILE_ELEMS;

#pragma unroll
        for (int ks = 0; ks < 2; ks++) {
            const int koff = ks * 16 + (lane & 3) * 2;
            const int nrow = wn * 32 + (lane >> 2);
            uint32_t bh0[4], bh1[4], bl0[4], bl1[4];
#pragma unroll
            for (int ni = 0; ni < 4; ni++) {
                int n = nrow + ni * 8;
                bh0[ni] = *(const uint32_t*)(Bhs + n * PB + koff);
                bh1[ni] = *(const uint32_t*)(Bhs + n * PB + koff + 8);
                bl0[ni] = *(const uint32_t*)(Bls + n * PB + koff);
                bl1[ni] = *(const uint32_t*)(Bls + n * PB + koff + 8);
            }
            const int arow = wm * 64 + (lane >> 2);
#pragma unroll
            for (int mi = 0; mi < 4; mi++) {
                int r = arow + mi * 16;
                uint32_t ah0 = *(const uint32_t*)(Ahs + r * PB + koff);
                uint32_t ah1 = *(const uint32_t*)(Ahs + (r + 8) * PB + koff);
                uint32_t ah2 = *(const uint32_t*)(Ahs + r * PB + koff + 8);
                uint32_t ah3 = *(const uint32_t*)(Ahs + (r + 8) * PB + koff + 8);
                uint32_t al0 = *(const uint32_t*)(Als + r * PB + koff);
                uint32_t al1 = *(const uint32_t*)(Als + (r + 8) * PB + koff);
                uint32_t al2 = *(const uint32_t*)(Als + r * PB + koff + 8);
                uint32_t al3 = *(const uint32_t*)(Als + (r + 8) * PB + koff + 8);
#pragma unroll
                for (int ni = 0; ni < 4; ni++) {
                    mma_bf16(acc[mi][ni], ah0, ah1, ah2, ah3, bh0[ni], bh1[ni]);
                    mma_bf16(acc[mi][ni], ah0, ah1, ah2, ah3, bl0[ni], bl1[ni]);
                    mma_bf16(acc[mi][ni], al0, al1, al2, al3, bh0[ni], bh1[ni]);
                }
            }
        }
        __syncthreads();
    }

    // Epilogue: bias + store/scatter. Element pairs are column-contiguous.
#pragma unroll
    for (int mi = 0; mi < 4; mi++) {
        int r0 = rowM + wm * 64 + mi * 16 + (lane >> 2);
#pragma unroll
        for (int ni = 0; ni < 4; ni++) {
            int c0 = rowN + wn * 32 + ni * 8 + (lane & 3) * 2;
            float bv0 = bias[c0], bv1 = bias[c0 + 1];
            float v00 = acc[mi][ni][0] + bv0, v01 = acc[mi][ni][1] + bv1;
            float v10 = acc[mi][ni][2] + bv0, v11 = acc[mi][ni][3] + bv1;
            if (MODE == 0) {
                int part = c0 >> 10, h = (c0 >> 6) & 15, l = c0 & 63;
#pragma unroll
                for (int rr = 0; rr < 2; rr++) {
                    int m = r0 + rr * 8;
                    int bb = m >> 11, n = m & (SEQ - 1);
                    int dst = ((bb * NH + h) * SEQ + n) * HD + l;
                    float x0 = rr ? v10 : v00, x1 = rr ? v11 : v01;
                    if (part == 0)      { g_Q[dst] = x0 * 0.125f; g_Q[dst + 1] = x1 * 0.125f; }
                    else if (part == 1) { g_K[dst] = x0;          g_K[dst + 1] = x1; }
                    else                { g_V[dst] = x0;          g_V[dst + 1] = x1; }
                }
            } else {
                float2 w0 = make_float2(v00, v01), w1 = make_float2(v10, v11);
                *(float2*)&C[(size_t)r0 * HID + c0]       = w0;
                *(float2*)&C[(size_t)(r0 + 8) * HID + c0] = w1;
            }
        }
    }
}

// ---------------- causal flash attention (proven fp32 kernel) --------------
#define APAD 68
__global__ __launch_bounds__(256) void attn_kernel(float* __restrict__ AO)
{
    extern __shared__ float smf[];
    float* QsT = smf;
    float* KsT = QsT + 64*APAD;
    float* Vs  = KsT + 64*APAD;
    float* PsT = Vs  + 64*APAD;

    const int qt = blockIdx.x, h = blockIdx.y, b = blockIdx.z;
    const int bh = b*NH + h;
    const float* Qg = g_Q + ((size_t)bh*SEQ + qt*64)*HD;
    const float* Kg = g_K + (size_t)bh*SEQ*HD;
    const float* Vg = g_V + (size_t)bh*SEQ*HD;

    const int tid = threadIdx.x;
    const int tk = tid & 15, tq = tid >> 4;
    const int q0 = tq*4, k0 = tk*4, d0 = tk*4;

#pragma unroll
    for (int t = 0; t < 4; t++) {
        int idx = t*256 + tid;
        int r = idx >> 4, c4 = (idx & 15) << 2;
        float4 v = *(const float4*)(Qg + r*HD + c4);
        QsT[(c4+0)*APAD + r] = v.x; QsT[(c4+1)*APAD + r] = v.y;
        QsT[(c4+2)*APAD + r] = v.z; QsT[(c4+3)*APAD + r] = v.w;
    }

    float mrow[4], lrow[4], O[4][4];
#pragma unroll
    for (int i = 0; i < 4; i++) {
        mrow[i] = -1e30f; lrow[i] = 0.0f;
#pragma unroll
        for (int j = 0; j < 4; j++) O[i][j] = 0.0f;
    }
    __syncthreads();

    for (int kt = 0; kt <= qt; kt++) {
        const float* Kt = Kg + (size_t)kt*64*HD;
        const float* Vt = Vg + (size_t)kt*64*HD;
#pragma unroll
        for (int t = 0; t < 4; t++) {
            int idx = t*256 + tid;
            int r = idx >> 4, c4 = (idx & 15) << 2;
            float4 kv = *(const float4*)(Kt + r*HD + c4);
            KsT[(c4+0)*APAD + r] = kv.x; KsT[(c4+1)*APAD + r] = kv.y;
            KsT[(c4+2)*APAD + r] = kv.z; KsT[(c4+3)*APAD + r] = kv.w;
            float4 vv = *(const float4*)(Vt + r*HD + c4);
            *(float4*)&Vs[r*APAD + c4] = vv;
        }
        __syncthreads();

        float s[4][4];
#pragma unroll
        for (int i = 0; i < 4; i++)
#pragma unroll
            for (int j = 0; j < 4; j++) s[i][j] = 0.0f;
#pragma unroll 8
        for (int d = 0; d < HD; d++) {
            float4 qv = *(float4*)&QsT[d*APAD + q0];
            float4 kv = *(float4*)&KsT[d*APAD + k0];
            float qr[4] = {qv.x, qv.y, qv.z, qv.w};
            float kr[4] = {kv.x, kv.y, kv.z, kv.w};
#pragma unroll
            for (int i = 0; i < 4; i++)
#pragma unroll
                for (int j = 0; j < 4; j++)
                    s[i][j] = fmaf(qr[i], kr[j], s[i][j]);
        }

        if (kt == qt) {
#pragma unroll
            for (int i = 0; i < 4; i++)
#pragma unroll
                for (int j = 0; j < 4; j++)
                    if (k0 + j > q0 + i) s[i][j] = -1e30f;
        }

#pragma unroll
        for (int i = 0; i < 4; i++) {
            float v = fmaxf(fmaxf(s[i][0], s[i][1]), fmaxf(s[i][2], s[i][3]));
#pragma unroll
            for (int off = 8; off >= 1; off >>= 1)
                v = fmaxf(v, __shfl_xor_sync(0xffffffffu, v, off, 16));
            float mn = fmaxf(mrow[i], v);
            float alpha = __expf(mrow[i] - mn);
#pragma unroll
            for (int j = 0; j < 4; j++) s[i][j] = __expf(s[i][j] - mn);
            float r = s[i][0] + s[i][1] + s[i][2] + s[i][3];
#pragma unroll
            for (int off = 8; off >= 1; off >>= 1)
                r += __shfl_xor_sync(0xffffffffu, r, off, 16);
            lrow[i] = lrow[i]*alpha + r;
            mrow[i] = mn;
#pragma unroll
            for (int j = 0; j < 4; j++) O[i][j] *= alpha;
        }

#pragma unroll
        for (int j = 0; j < 4; j++)
#pragma unroll
            for (int i = 0; i < 4; i++)
                PsT[(k0+j)*APAD + q0 + i] = s[i][j];
        __syncthreads();

#pragma unroll 8
        for (int k = 0; k < 64; k++) {
            float4 pv = *(float4*)&PsT[k*APAD + q0];
            float4 vv = *(float4*)&Vs[k*APAD + d0];
            float pr[4] = {pv.x, pv.y, pv.z, pv.w};
            float vr[4] = {vv.x, vv.y, vv.z, vv.w};
#pragma unroll
            for (int i = 0; i < 4; i++)
#pragma unroll
                for (int j = 0; j < 4; j++)
                    O[i][j] = fmaf(pr[i], vr[j], O[i][j]);
        }
        __syncthreads();
    }

#pragma unroll
    for (int i = 0; i < 4; i++) {
        float inv = 1.0f / lrow[i];
        int qglob = qt*64 + q0 + i;
        float* dst = AO + ((size_t)(b*SEQ + qglob))*HID + h*HD + d0;
#pragma unroll
        for (int j = 0; j < 4; j++) dst[j] = O[i][j] * inv;
    }
}

// ---------------------------------------------------------------------------
extern "C" void kernel_launch(void* const* d_in, const int* in_sizes, int n_in,
                              void* d_out, int out_size)
{
    const float* enc    = (const float*)d_in[0];
    const float* W_attn = (const float*)d_in[1];
    const float* b_attn = (const float*)d_in[2];
    const float* W_out  = (const float*)d_in[3];
    const float* b_out  = (const float*)d_in[4];
    float* out = (float*)d_out;

    float* d_AO; cudaGetSymbolAddress((void**)&d_AO, g_AO);
    __nv_bfloat16 *d_Ah, *d_Al, *d_WqTh, *d_WqTl, *d_WoTh, *d_WoTl, *d_AOh, *d_AOl;
    cudaGetSymbolAddress((void**)&d_Ah,   g_Ah);
    cudaGetSymbolAddress((void**)&d_Al,   g_Al);
    cudaGetSymbolAddress((void**)&d_WqTh, g_WqTh);
    cudaGetSymbolAddress((void**)&d_WqTl, g_WqTl);
    cudaGetSymbolAddress((void**)&d_WoTh, g_WoTh);
    cudaGetSymbolAddress((void**)&d_WoTl, g_WoTl);
    cudaGetSymbolAddress((void**)&d_AOh,  g_AOh);
    cudaGetSymbolAddress((void**)&d_AOl,  g_AOl);

    const size_t gsmem = (size_t)2 * BUF_ELEMS * sizeof(__nv_bfloat16);  // 81920 B
    cudaFuncSetAttribute(gemm_mma<0>, cudaFuncAttributeMaxDynamicSharedMemorySize, (int)gsmem);
    cudaFuncSetAttribute(gemm_mma<1>, cudaFuncAttributeMaxDynamicSharedMemorySize, (int)gsmem);

    // 0) prep: split enc, transpose+split weights
    split_kernel<<<(MTOK*HID/4 + 255)/256, 256>>>((const float4*)enc, d_Ah, d_Al, MTOK*HID/4);
    transpose_split<<<dim3(3*HID/32, HID/32), dim3(32,8)>>>(W_attn, d_WqTh, d_WqTl, HID, 3*HID);
    transpose_split<<<dim3(HID/32, HID/32),   dim3(32,8)>>>(W_out,  d_WoTh, d_WoTl, HID, HID);

    // 1) QKV projection (HMMA) + head-major scatter
    gemm_mma<0><<<dim3(3*HID/128, MTOK/128), 256, gsmem>>>(d_Ah, d_Al, d_WqTh, d_WqTl,
                                                           b_attn, nullptr);

    // 2) causal attention (fp32)
    {
        size_t smem = (size_t)4 * 64 * APAD * sizeof(float);
        cudaFuncSetAttribute(attn_kernel, cudaFuncAttributeMaxDynamicSharedMemorySize, (int)smem);
        attn_kernel<<<dim3(SEQ/64, NH, BATCH), 256, smem>>>(d_AO);
    }

    // 3) split attention output, then output projection (HMMA)
    split_kernel<<<(MTOK*HID/4 + 255)/256, 256>>>((const float4*)d_AO, d_AOh, d_AOl, MTOK*HID/4);
    gemm_mma<1><<<dim3(HID/128, MTOK/128), 256, gsmem>>>(d_AOh, d_AOl, d_WoTh, d_WoTl,
                                                         b_out, out);
}

// round 14
// speedup vs baseline: 2.2350x; 1.7015x over previous
#include <cuda_runtime.h>
#include <cuda_bf16.h>
#include <stdint.h>
#include <math.h>

#define SEQ   2048
#define BATCH 2
#define HID   1024
#define NH    16
#define HD    64
#define MTOK  (BATCH*SEQ)   // 4096

// ---------------- scratch (allocation-free) ----------------
__device__ float g_AO[MTOK*HID];
__device__ __nv_bfloat16 g_Ah[MTOK*HID],    g_Al[MTOK*HID];      // enc split
__device__ __nv_bfloat16 g_WqTh[3*HID*HID], g_WqTl[3*HID*HID];   // W_attn^T split
__device__ __nv_bfloat16 g_WoTh[HID*HID],   g_WoTl[HID*HID];     // W_out^T split
__device__ __nv_bfloat16 g_AOh[MTOK*HID],   g_AOl[MTOK*HID];     // attn out split
// head-major bf16 split Q/K/V ([bh][n][d]); Q pre-scaled by 1/8
__device__ __nv_bfloat16 g_Qh[BATCH*NH*SEQ*HD], g_Ql[BATCH*NH*SEQ*HD];
__device__ __nv_bfloat16 g_Kh[BATCH*NH*SEQ*HD], g_Kl[BATCH*NH*SEQ*HD];
__device__ __nv_bfloat16 g_Vh[BATCH*NH*SEQ*HD], g_Vl[BATCH*NH*SEQ*HD];

__device__ __forceinline__ uint32_t smem_u32(const void* p) {
    uint32_t a;
    asm("{ .reg .u64 t; cvta.to.shared.u64 t, %1; cvt.u32.u64 %0, t; }" : "=r"(a) : "l"(p));
    return a;
}

__device__ __forceinline__ void mma_bf16(float* d,
                                         uint32_t a0, uint32_t a1, uint32_t a2, uint32_t a3,
                                         uint32_t b0, uint32_t b1) {
    asm volatile("mma.sync.aligned.m16n8k16.row.col.f32.bf16.bf16.f32 "
                 "{%0,%1,%2,%3}, {%4,%5,%6,%7}, {%8,%9}, {%0,%1,%2,%3};"
                 : "+f"(d[0]), "+f"(d[1]), "+f"(d[2]), "+f"(d[3])
                 : "r"(a0), "r"(a1), "r"(a2), "r"(a3), "r"(b0), "r"(b1));
}

#define LDM4(r0,r1,r2,r3, a) \
    asm volatile("ldmatrix.sync.aligned.m8n8.x4.shared.b16 {%0,%1,%2,%3}, [%4];" \
        : "=r"(r0),"=r"(r1),"=r"(r2),"=r"(r3) : "r"(a))
#define LDM4T(r0,r1,r2,r3, a) \
    asm volatile("ldmatrix.sync.aligned.m8n8.x4.trans.shared.b16 {%0,%1,%2,%3}, [%4];" \
        : "=r"(r0),"=r"(r1),"=r"(r2),"=r"(r3) : "r"(a))

// split fp32 pair -> hi/lo bf16x2 (low half = first element)
__device__ __forceinline__ void split2(float x, float y, uint32_t& hi, uint32_t& lo) {
    __nv_bfloat162 t = __floats2bfloat162_rn(x, y);
    hi = *(uint32_t*)&t;
    float xr = x - __bfloat162float(t.x);
    float yr = y - __bfloat162float(t.y);
    __nv_bfloat162 u = __floats2bfloat162_rn(xr, yr);
    lo = *(uint32_t*)&u;
}

// ---------------- split / transpose-split ----------------
__global__ void split_kernel(const float4* __restrict__ src,
                             __nv_bfloat16* __restrict__ h,
                             __nv_bfloat16* __restrict__ l, int n4)
{
    int i = blockIdx.x * blockDim.x + threadIdx.x;
    if (i >= n4) return;
    float4 v = src[i];
    float a[4] = {v.x, v.y, v.z, v.w};
#pragma unroll
    for (int j = 0; j < 4; j++) {
        __nv_bfloat16 hi = __float2bfloat16(a[j]);
        h[4*i + j] = hi;
        l[4*i + j] = __float2bfloat16(a[j] - __bfloat162float(hi));
    }
}

__global__ void transpose_split(const float* __restrict__ W,
                                __nv_bfloat16* __restrict__ Th,
                                __nv_bfloat16* __restrict__ Tl, int K, int N)
{
    __shared__ float t[32][33];
    int bn = blockIdx.x * 32, bk = blockIdx.y * 32;
    int tx = threadIdx.x, ty = threadIdx.y;
#pragma unroll
    for (int j = 0; j < 32; j += 8)
        t[ty + j][tx] = W[(size_t)(bk + ty + j) * N + bn + tx];
    __syncthreads();
#pragma unroll
    for (int j = 0; j < 32; j += 8) {
        float v = t[tx][ty + j];
        __nv_bfloat16 hi = __float2bfloat16(v);
        size_t o = (size_t)(bn + ty + j) * K + bk + tx;
        Th[o] = hi;
        Tl[o] = __float2bfloat16(v - __bfloat162float(hi));
    }
}

// ---------------------------------------------------------------------------
// Split-bf16 HMMA GEMM: C[4096, N] = A @ B^T + bias  (hh+hl+lh)
// MODE 0: qkv epilogue -> bf16 split head-major Q(*0.125)/K/V. MODE 1: fp32 C.
// ---------------------------------------------------------------------------
#define PB 40
#define TILE_ELEMS (128*PB)
#define BUF_ELEMS  (4*TILE_ELEMS)

template<int MODE>
__global__ __launch_bounds__(256, 1) void gemm_mma(
    const __nv_bfloat16* __restrict__ Ah, const __nv_bfloat16* __restrict__ Al,
    const __nv_bfloat16* __restrict__ Bh, const __nv_bfloat16* __restrict__ Bl,
    const float* __restrict__ bias, float* __restrict__ C)
{
    extern __shared__ __nv_bfloat16 sm[];
    const int tid = threadIdx.x, lane = tid & 31, warp = tid >> 5;
    const int wm = warp >> 2, wn = warp & 3;
    const int rowM = blockIdx.y * 128, rowN = blockIdx.x * 128;
    const uint32_t sbase = smem_u32(sm);

    float acc[4][4][4];
#pragma unroll
    for (int a = 0; a < 4; a++)
#pragma unroll
        for (int b = 0; b < 4; b++)
#pragma unroll
            for (int c = 0; c < 4; c++) acc[a][b][c] = 0.0f;

    const __nv_bfloat16* gsrc[4] = {Ah, Al, Bh, Bl};
    const int rb[4] = {rowM, rowM, rowN, rowN};

    auto issue = [&](int ch, int buf) {
#pragma unroll
        for (int t4 = 0; t4 < 4; t4++) {
#pragma unroll
            for (int t = 0; t < 2; t++) {
                int idx = t * 256 + tid;
                int r = idx >> 2, cqk = idx & 3;
                const __nv_bfloat16* g = gsrc[t4] + (size_t)(rb[t4] + r) * HID + ch * 32 + cqk * 8;
                uint32_t s = sbase + (uint32_t)(buf * BUF_ELEMS + t4 * TILE_ELEMS) * 2u
                                   + (uint32_t)(r * (PB * 2) + cqk * 16);
                asm volatile("cp.async.cg.shared.global [%0], [%1], 16;\n" :: "r"(s), "l"(g));
            }
        }
        asm volatile("cp.async.commit_group;\n" ::: "memory");
    };

    issue(0, 0);

    const int NC = HID / 32;
    for (int ch = 0; ch < NC; ch++) {
        if (ch + 1 < NC) {
            issue(ch + 1, (ch + 1) & 1);
            asm volatile("cp.async.wait_group 1;\n" ::: "memory");
        } else {
            asm volatile("cp.async.wait_group 0;\n" ::: "memory");
        }
        __syncthreads();

        const __nv_bfloat16* base = sm + (ch & 1) * BUF_ELEMS;
        const __nv_bfloat16* Ahs = base;
        const __nv_bfloat16* Als = base + TILE_ELEMS;
        const __nv_bfloat16* Bhs = base + 2 * TILE_ELEMS;
        const __nv_bfloat16* Bls = base + 3 * TILE_ELEMS;

#pragma unroll
        for (int ks = 0; ks < 2; ks++) {
            const int koff = ks * 16 + (lane & 3) * 2;
            const int nrow = wn * 32 + (lane >> 2);
            uint32_t bh0[4], bh1[4], bl0[4], bl1[4];
#pragma unroll
            for (int ni = 0; ni < 4; ni++) {
                int n = nrow + ni * 8;
                bh0[ni] = *(const uint32_t*)(Bhs + n * PB + koff);
                bh1[ni] = *(const uint32_t*)(Bhs + n * PB + koff + 8);
                bl0[ni] = *(const uint32_t*)(Bls + n * PB + koff);
                bl1[ni] = *(const uint32_t*)(Bls + n * PB + koff + 8);
            }
            const int arow = wm * 64 + (lane >> 2);
#pragma unroll
            for (int mi = 0; mi < 4; mi++) {
                int r = arow + mi * 16;
                uint32_t ah0 = *(const uint32_t*)(Ahs + r * PB + koff);
                uint32_t ah1 = *(const uint32_t*)(Ahs + (r + 8) * PB + koff);
                uint32_t ah2 = *(const uint32_t*)(Ahs + r * PB + koff + 8);
                uint32_t ah3 = *(const uint32_t*)(Ahs + (r + 8) * PB + koff + 8);
                uint32_t al0 = *(const uint32_t*)(Als + r * PB + koff);
                uint32_t al1 = *(const uint32_t*)(Als + (r + 8) * PB + koff);
                uint32_t al2 = *(const uint32_t*)(Als + r * PB + koff + 8);
                uint32_t al3 = *(const uint32_t*)(Als + (r + 8) * PB + koff + 8);
#pragma unroll
                for (int ni = 0; ni < 4; ni++) {
                    mma_bf16(acc[mi][ni], ah0, ah1, ah2, ah3, bh0[ni], bh1[ni]);
                    mma_bf16(acc[mi][ni], ah0, ah1, ah2, ah3, bl0[ni], bl1[ni]);
                    mma_bf16(acc[mi][ni], al0, al1, al2, al3, bh0[ni], bh1[ni]);
                }
            }
        }
        __syncthreads();
    }

#pragma unroll
    for (int mi = 0; mi < 4; mi++) {
        int r0 = rowM + wm * 64 + mi * 16 + (lane >> 2);
#pragma unroll
        for (int ni = 0; ni < 4; ni++) {
            int c0 = rowN + wn * 32 + ni * 8 + (lane & 3) * 2;
            float bv0 = bias[c0], bv1 = bias[c0 + 1];
            float v00 = acc[mi][ni][0] + bv0, v01 = acc[mi][ni][1] + bv1;
            float v10 = acc[mi][ni][2] + bv0, v11 = acc[mi][ni][3] + bv1;
            if (MODE == 0) {
                int part = c0 >> 10, hh = (c0 >> 6) & 15, l = c0 & 63;
#pragma unroll
                for (int rr = 0; rr < 2; rr++) {
                    int m = r0 + rr * 8;
                    int bb = m >> 11, n = m & (SEQ - 1);
                    size_t dst = ((size_t)(bb * NH + hh) * SEQ + n) * HD + l;
                    float x0 = rr ? v10 : v00, x1 = rr ? v11 : v01;
                    uint32_t hi, lo;
                    if (part == 0) {
                        split2(x0 * 0.125f, x1 * 0.125f, hi, lo);
                        *(uint32_t*)&g_Qh[dst] = hi; *(uint32_t*)&g_Ql[dst] = lo;
                    } else if (part == 1) {
                        split2(x0, x1, hi, lo);
                        *(uint32_t*)&g_Kh[dst] = hi; *(uint32_t*)&g_Kl[dst] = lo;
                    } else {
                        split2(x0, x1, hi, lo);
                        *(uint32_t*)&g_Vh[dst] = hi; *(uint32_t*)&g_Vl[dst] = lo;
                    }
                }
            } else {
                *(float2*)&C[(size_t)r0 * HID + c0]       = make_float2(v00, v01);
                *(float2*)&C[(size_t)(r0 + 8) * HID + c0] = make_float2(v10, v11);
            }
        }
    }
}

// ---------------------------------------------------------------------------
// HMMA causal flash attention. CTA = 128 queries of one (b,h); 8 warps x 16 rows.
// S = Q.K^T and O += P.V as split-bf16 3-product MMAs; softmax in accumulator
// layout; P repacked to A-fragments in registers (no smem round-trip).
// ---------------------------------------------------------------------------
__global__ __launch_bounds__(256, 1) void attn_mma(float* __restrict__ AO)
{
    __shared__ __nv_bfloat16 Ksh[64*72], Ksl[64*72], Vsh[64*72], Vsl[64*72];
    const int tid = threadIdx.x, lane = tid & 31, warp = tid >> 5;
    const int qt = (int)(gridDim.x - 1 - blockIdx.x);   // heavy tiles first
    const int hh = blockIdx.y, bb = blockIdx.z;
    const int bh = bb * NH + hh;
    const int qbase = qt * 128;
    const int rq = lane >> 2, cq = (lane & 3) * 2;
    const int row0 = qbase + warp * 16 + rq;
    const int lt = lane >> 3, lr = lane & 7;

    // Q fragments (hi/lo), resident for the whole kernel
    uint32_t qh[4][4], ql[4][4];
    {
        const uint32_t* Qh32 = (const uint32_t*)g_Qh + (size_t)bh * SEQ * HD / 2;
        const uint32_t* Ql32 = (const uint32_t*)g_Ql + (size_t)bh * SEQ * HD / 2;
        int r0 = row0, r1 = row0 + 8;
#pragma unroll
        for (int ks = 0; ks < 4; ks++) {
            int d0 = ks * 16 + cq;
            qh[ks][0] = Qh32[(r0 * HD + d0) >> 1];
            qh[ks][1] = Qh32[(r1 * HD + d0) >> 1];
            qh[ks][2] = Qh32[(r0 * HD + d0 + 8) >> 1];
            qh[ks][3] = Qh32[(r1 * HD + d0 + 8) >> 1];
            ql[ks][0] = Ql32[(r0 * HD + d0) >> 1];
            ql[ks][1] = Ql32[(r1 * HD + d0) >> 1];
            ql[ks][2] = Ql32[(r0 * HD + d0 + 8) >> 1];
            ql[ks][3] = Ql32[(r1 * HD + d0 + 8) >> 1];
        }
    }

    float o[8][4];
#pragma unroll
    for (int i = 0; i < 8; i++)
#pragma unroll
        for (int j = 0; j < 4; j++) o[i][j] = 0.0f;
    float m2[2] = {-1e30f, -1e30f}, l2[2] = {0.0f, 0.0f};

    const uint32_t sKh = smem_u32(Ksh), sKl = smem_u32(Ksl);
    const uint32_t sVh = smem_u32(Vsh), sVl = smem_u32(Vsl);
    // per-lane ldmatrix base offsets (bytes)
    const uint32_t kOff = (uint32_t)(((lr + ((lt >> 1) << 3)) * 72 + ((lt & 1) << 3)) * 2);
    const uint32_t vOff = (uint32_t)(((lr + ((lt & 1) << 3)) * 72 + ((lt >> 1) << 3)) * 2);

    const int NKT = 2 * qt + 2;
    for (int kt = 0; kt < NKT; kt++) {
        {   // stage K/V hi/lo tiles (64x64), row-major, pitch 72
            size_t gb = (size_t)(bh * SEQ + kt * 64) * HD;
            const uint4* s0 = (const uint4*)(g_Kh + gb);
            const uint4* s1 = (const uint4*)(g_Kl + gb);
            const uint4* s2 = (const uint4*)(g_Vh + gb);
            const uint4* s3 = (const uint4*)(g_Vl + gb);
#pragma unroll
            for (int t = 0; t < 2; t++) {
                int idx = t * 256 + tid;
                int r = idx >> 3, c = idx & 7;
                *(uint4*)&Ksh[r * 72 + c * 8] = s0[r * 8 + c];
                *(uint4*)&Ksl[r * 72 + c * 8] = s1[r * 8 + c];
                *(uint4*)&Vsh[r * 72 + c * 8] = s2[r * 8 + c];
                *(uint4*)&Vsl[r * 72 + c * 8] = s3[r * 8 + c];
            }
        }
        __syncthreads();

        // ---- S = Q.K^T (3-product) ----
        float s[8][4];
#pragma unroll
        for (int i = 0; i < 8; i++)
#pragma unroll
            for (int j = 0; j < 4; j++) s[i][j] = 0.0f;
#pragma unroll
        for (int ks = 0; ks < 4; ks++) {
#pragma unroll
            for (int p = 0; p < 4; p++) {
                uint32_t off = (uint32_t)((p * 16 * 72 + ks * 16) * 2);
                uint32_t kh0, kh1, kh2, kh3, kl0, kl1, kl2, kl3;
                LDM4(kh0, kh1, kh2, kh3, sKh + kOff + off);
                LDM4(kl0, kl1, kl2, kl3, sKl + kOff + off);
                mma_bf16(s[2*p],   qh[ks][0], qh[ks][1], qh[ks][2], qh[ks][3], kh0, kh1);
                mma_bf16(s[2*p],   qh[ks][0], qh[ks][1], qh[ks][2], qh[ks][3], kl0, kl1);
                mma_bf16(s[2*p],   ql[ks][0], ql[ks][1], ql[ks][2], ql[ks][3], kh0, kh1);
                mma_bf16(s[2*p+1], qh[ks][0], qh[ks][1], qh[ks][2], qh[ks][3], kh2, kh3);
                mma_bf16(s[2*p+1], qh[ks][0], qh[ks][1], qh[ks][2], qh[ks][3], kl2, kl3);
                mma_bf16(s[2*p+1], ql[ks][0], ql[ks][1], ql[ks][2], ql[ks][3], kh2, kh3);
            }
        }

        // ---- causal mask (only tiles crossing the diagonal) ----
        if (kt >= 2 * qt) {
            int kb = kt * 64;
#pragma unroll
            for (int ni = 0; ni < 8; ni++)
#pragma unroll
                for (int c = 0; c < 4; c++) {
                    int key = kb + ni * 8 + cq + (c & 1);
                    int qr  = row0 + ((c >> 1) << 3);
                    if (key > qr) s[ni][c] = -1e30f;
                }
        }

        // ---- online softmax in accumulator layout ----
#pragma unroll
        for (int half = 0; half < 2; half++) {
            float mx = -1e30f;
#pragma unroll
            for (int ni = 0; ni < 8; ni++)
                mx = fmaxf(mx, fmaxf(s[ni][half*2], s[ni][half*2+1]));
            mx = fmaxf(mx, __shfl_xor_sync(0xffffffffu, mx, 1));
            mx = fmaxf(mx, __shfl_xor_sync(0xffffffffu, mx, 2));
            float mn = fmaxf(m2[half], mx);
            float alpha = __expf(m2[half] - mn);
            float sum = 0.0f;
#pragma unroll
            for (int ni = 0; ni < 8; ni++) {
                float e0 = __expf(s[ni][half*2]   - mn);
                float e1 = __expf(s[ni][half*2+1] - mn);
                s[ni][half*2] = e0; s[ni][half*2+1] = e1;
                sum += e0 + e1;
            }
            sum += __shfl_xor_sync(0xffffffffu, sum, 1);
            sum += __shfl_xor_sync(0xffffffffu, sum, 2);
            l2[half] = l2[half] * alpha + sum;
            m2[half] = mn;
#pragma unroll
            for (int dn = 0; dn < 8; dn++) {
                o[dn][half*2]   *= alpha;
                o[dn][half*2+1] *= alpha;
            }
        }

        // ---- repack P (accumulator -> A fragments), split hi/lo ----
        uint32_t ph[4][4], pl[4][4];
#pragma unroll
        for (int k2 = 0; k2 < 4; k2++) {
            int n0 = 2 * k2, n1 = n0 + 1;
            split2(s[n0][0], s[n0][1], ph[k2][0], pl[k2][0]);
            split2(s[n0][2], s[n0][3], ph[k2][1], pl[k2][1]);
            split2(s[n1][0], s[n1][1], ph[k2][2], pl[k2][2]);
            split2(s[n1][2], s[n1][3], ph[k2][3], pl[k2][3]);
        }

        // ---- O += P.V (3-product, ldmatrix.trans for V) ----
#pragma unroll
        for (int k2 = 0; k2 < 4; k2++) {
#pragma unroll
            for (int p = 0; p < 4; p++) {
                uint32_t off = (uint32_t)((k2 * 16 * 72 + p * 16) * 2);
                uint32_t vh0, vh1, vh2, vh3, vl0, vl1, vl2, vl3;
                LDM4T(vh0, vh1, vh2, vh3, sVh + vOff + off);
                LDM4T(vl0, vl1, vl2, vl3, sVl + vOff + off);
                mma_bf16(o[2*p],   ph[k2][0], ph[k2][1], ph[k2][2], ph[k2][3], vh0, vh1);
                mma_bf16(o[2*p],   ph[k2][0], ph[k2][1], ph[k2][2], ph[k2][3], vl0, vl1);
                mma_bf16(o[2*p],   pl[k2][0], pl[k2][1], pl[k2][2], pl[k2][3], vh0, vh1);
                mma_bf16(o[2*p+1], ph[k2][0], ph[k2][1], ph[k2][2], ph[k2][3], vh2, vh3);
                mma_bf16(o[2*p+1], ph[k2][0], ph[k2][1], ph[k2][2], ph[k2][3], vl2, vl3);
                mma_bf16(o[2*p+1], pl[k2][0], pl[k2][1], pl[k2][2], pl[k2][3], vh2, vh3);
            }
        }
        __syncthreads();
    }

    // ---- normalize + write [b, n, h*64+d] ----
#pragma unroll
    for (int half = 0; half < 2; half++) {
        float inv = 1.0f / l2[half];
        int row = row0 + half * 8;
        float* dst = AO + ((size_t)(bb * SEQ + row)) * HID + hh * HD;
#pragma unroll
        for (int dn = 0; dn < 8; dn++) {
            *(float2*)(dst + dn * 8 + cq) =
                make_float2(o[dn][half*2] * inv, o[dn][half*2+1] * inv);
        }
    }
}

// ---------------------------------------------------------------------------
extern "C" void kernel_launch(void* const* d_in, const int* in_sizes, int n_in,
                              void* d_out, int out_size)
{
    const float* enc    = (const float*)d_in[0];
    const float* W_attn = (const float*)d_in[1];
    const float* b_attn = (const float*)d_in[2];
    const float* W_out  = (const float*)d_in[3];
    const float* b_out  = (const float*)d_in[4];
    float* out = (float*)d_out;

    float* d_AO; cudaGetSymbolAddress((void**)&d_AO, g_AO);
    __nv_bfloat16 *d_Ah, *d_Al, *d_WqTh, *d_WqTl, *d_WoTh, *d_WoTl, *d_AOh, *d_AOl;
    cudaGetSymbolAddress((void**)&d_Ah,   g_Ah);
    cudaGetSymbolAddress((void**)&d_Al,   g_Al);
    cudaGetSymbolAddress((void**)&d_WqTh, g_WqTh);
    cudaGetSymbolAddress((void**)&d_WqTl, g_WqTl);
    cudaGetSymbolAddress((void**)&d_WoTh, g_WoTh);
    cudaGetSymbolAddress((void**)&d_WoTl, g_WoTl);
    cudaGetSymbolAddress((void**)&d_AOh,  g_AOh);
    cudaGetSymbolAddress((void**)&d_AOl,  g_AOl);

    const size_t gsmem = (size_t)2 * BUF_ELEMS * sizeof(__nv_bfloat16);  // 81920 B
    cudaFuncSetAttribute(gemm_mma<0>, cudaFuncAttributeMaxDynamicSharedMemorySize, (int)gsmem);
    cudaFuncSetAttribute(gemm_mma<1>, cudaFuncAttributeMaxDynamicSharedMemorySize, (int)gsmem);

    // 0) prep: split enc, transpose+split weights
    split_kernel<<<(MTOK*HID/4 + 255)/256, 256>>>((const float4*)enc, d_Ah, d_Al, MTOK*HID/4);
    transpose_split<<<dim3(3*HID/32, HID/32), dim3(32,8)>>>(W_attn, d_WqTh, d_WqTl, HID, 3*HID);
    transpose_split<<<dim3(HID/32, HID/32),   dim3(32,8)>>>(W_out,  d_WoTh, d_WoTl, HID, HID);

    // 1) QKV projection (HMMA) -> split bf16 head-major Q/K/V
    gemm_mma<0><<<dim3(3*HID/128, MTOK/128), 256, gsmem>>>(d_Ah, d_Al, d_WqTh, d_WqTl,
                                                           b_attn, nullptr);

    // 2) causal attention (HMMA)
    attn_mma<<<dim3(SEQ/128, NH, BATCH), 256>>>(d_AO);

    // 3) split attention output, then output projection (HMMA)
    split_kernel<<<(MTOK*HID/4 + 255)/256, 256>>>((const float4*)d_AO, d_AOh, d_AOl, MTOK*HID/4);
    gemm_mma<1><<<dim3(HID/128, MTOK/128), 256, gsmem>>>(d_AOh, d_AOl, d_WoTh, d_WoTl,
                                                         b_out, out);
}

// round 15
// speedup vs baseline: 2.3412x; 1.0475x over previous
#include <cuda_runtime.h>
#include <cuda_bf16.h>
#include <stdint.h>
#include <math.h>

#define SEQ   2048
#define BATCH 2
#define HID   1024
#define NH    16
#define HD    64
#define MTOK  (BATCH*SEQ)   // 4096

// ---------------- scratch (allocation-free) ----------------
__device__ __nv_bfloat16 g_Ah[MTOK*HID],    g_Al[MTOK*HID];      // enc split
__device__ __nv_bfloat16 g_WqTh[3*HID*HID], g_WqTl[3*HID*HID];   // W_attn^T split
__device__ __nv_bfloat16 g_WoTh[HID*HID],   g_WoTl[HID*HID];     // W_out^T split
__device__ __nv_bfloat16 g_AOh[MTOK*HID],   g_AOl[MTOK*HID];     // attn out split
// head-major bf16 split Q/K/V ([bh][n][d]); Q pre-scaled by 1/8
__device__ __nv_bfloat16 g_Qh[BATCH*NH*SEQ*HD], g_Ql[BATCH*NH*SEQ*HD];
__device__ __nv_bfloat16 g_Kh[BATCH*NH*SEQ*HD], g_Kl[BATCH*NH*SEQ*HD];
__device__ __nv_bfloat16 g_Vh[BATCH*NH*SEQ*HD], g_Vl[BATCH*NH*SEQ*HD];

__device__ __forceinline__ uint32_t smem_u32(const void* p) {
    uint32_t a;
    asm("{ .reg .u64 t; cvta.to.shared.u64 t, %1; cvt.u32.u64 %0, t; }" : "=r"(a) : "l"(p));
    return a;
}

__device__ __forceinline__ void mma_bf16(float* d,
                                         uint32_t a0, uint32_t a1, uint32_t a2, uint32_t a3,
                                         uint32_t b0, uint32_t b1) {
    asm volatile("mma.sync.aligned.m16n8k16.row.col.f32.bf16.bf16.f32 "
                 "{%0,%1,%2,%3}, {%4,%5,%6,%7}, {%8,%9}, {%0,%1,%2,%3};"
                 : "+f"(d[0]), "+f"(d[1]), "+f"(d[2]), "+f"(d[3])
                 : "r"(a0), "r"(a1), "r"(a2), "r"(a3), "r"(b0), "r"(b1));
}

#define LDM4(r0,r1,r2,r3, a) \
    asm volatile("ldmatrix.sync.aligned.m8n8.x4.shared.b16 {%0,%1,%2,%3}, [%4];" \
        : "=r"(r0),"=r"(r1),"=r"(r2),"=r"(r3) : "r"(a))
#define LDM4T(r0,r1,r2,r3, a) \
    asm volatile("ldmatrix.sync.aligned.m8n8.x4.trans.shared.b16 {%0,%1,%2,%3}, [%4];" \
        : "=r"(r0),"=r"(r1),"=r"(r2),"=r"(r3) : "r"(a))

// split fp32 pair -> hi/lo bf16x2
__device__ __forceinline__ void split2(float x, float y, uint32_t& hi, uint32_t& lo) {
    __nv_bfloat162 t = __floats2bfloat162_rn(x, y);
    hi = *(uint32_t*)&t;
    float xr = x - __bfloat162float(t.x);
    float yr = y - __bfloat162float(t.y);
    __nv_bfloat162 u = __floats2bfloat162_rn(xr, yr);
    lo = *(uint32_t*)&u;
}

// ---------------- split / transpose-split ----------------
__global__ void split_kernel(const float4* __restrict__ src,
                             __nv_bfloat16* __restrict__ h,
                             __nv_bfloat16* __restrict__ l, int n4)
{
    int i = blockIdx.x * blockDim.x + threadIdx.x;
    if (i >= n4) return;
    float4 v = src[i];
    float a[4] = {v.x, v.y, v.z, v.w};
#pragma unroll
    for (int j = 0; j < 4; j++) {
        __nv_bfloat16 hi = __float2bfloat16(a[j]);
        h[4*i + j] = hi;
        l[4*i + j] = __float2bfloat16(a[j] - __bfloat162float(hi));
    }
}

__global__ void transpose_split(const float* __restrict__ W,
                                __nv_bfloat16* __restrict__ Th,
                                __nv_bfloat16* __restrict__ Tl, int K, int N)
{
    __shared__ float t[32][33];
    int bn = blockIdx.x * 32, bk = blockIdx.y * 32;
    int tx = threadIdx.x, ty = threadIdx.y;
#pragma unroll
    for (int j = 0; j < 32; j += 8)
        t[ty + j][tx] = W[(size_t)(bk + ty + j) * N + bn + tx];
    __syncthreads();
#pragma unroll
    for (int j = 0; j < 32; j += 8) {
        float v = t[tx][ty + j];
        __nv_bfloat16 hi = __float2bfloat16(v);
        size_t o = (size_t)(bn + ty + j) * K + bk + tx;
        Th[o] = hi;
        Tl[o] = __float2bfloat16(v - __bfloat162float(hi));
    }
}

// ---------------------------------------------------------------------------
// Split-bf16 HMMA GEMM: C[4096, N] = A @ B^T + bias  (hh+hl+lh)
// MODE 0: qkv epilogue -> bf16 split head-major Q(*0.125)/K/V. MODE 1: fp32 C.
// 2 CTAs/SM (reg cap 128); product-major MMA ordering (dep distance 4).
// ---------------------------------------------------------------------------
#define PB 40
#define TILE_ELEMS (128*PB)
#define BUF_ELEMS  (4*TILE_ELEMS)

template<int MODE>
__global__ __launch_bounds__(256, 2) void gemm_mma(
    const __nv_bfloat16* __restrict__ Ah, const __nv_bfloat16* __restrict__ Al,
    const __nv_bfloat16* __restrict__ Bh, const __nv_bfloat16* __restrict__ Bl,
    const float* __restrict__ bias, float* __restrict__ C)
{
    extern __shared__ __nv_bfloat16 sm[];
    const int tid = threadIdx.x, lane = tid & 31, warp = tid >> 5;
    const int wm = warp >> 2, wn = warp & 3;
    const int rowM = blockIdx.y * 128, rowN = blockIdx.x * 128;
    const uint32_t sbase = smem_u32(sm);

    float acc[4][4][4];
#pragma unroll
    for (int a = 0; a < 4; a++)
#pragma unroll
        for (int b = 0; b < 4; b++)
#pragma unroll
            for (int c = 0; c < 4; c++) acc[a][b][c] = 0.0f;

    const __nv_bfloat16* gsrc[4] = {Ah, Al, Bh, Bl};
    const int rb[4] = {rowM, rowM, rowN, rowN};

    auto issue = [&](int ch, int buf) {
#pragma unroll
        for (int t4 = 0; t4 < 4; t4++) {
#pragma unroll
            for (int t = 0; t < 2; t++) {
                int idx = t * 256 + tid;
                int r = idx >> 2, cqk = idx & 3;
                const __nv_bfloat16* g = gsrc[t4] + (size_t)(rb[t4] + r) * HID + ch * 32 + cqk * 8;
                uint32_t s = sbase + (uint32_t)(buf * BUF_ELEMS + t4 * TILE_ELEMS) * 2u
                                   + (uint32_t)(r * (PB * 2) + cqk * 16);
                asm volatile("cp.async.cg.shared.global [%0], [%1], 16;\n" :: "r"(s), "l"(g));
            }
        }
        asm volatile("cp.async.commit_group;\n" ::: "memory");
    };

    issue(0, 0);

    const int NC = HID / 32;
    for (int ch = 0; ch < NC; ch++) {
        if (ch + 1 < NC) {
            issue(ch + 1, (ch + 1) & 1);
            asm volatile("cp.async.wait_group 1;\n" ::: "memory");
        } else {
            asm volatile("cp.async.wait_group 0;\n" ::: "memory");
        }
        __syncthreads();

        const __nv_bfloat16* base = sm + (ch & 1) * BUF_ELEMS;
        const __nv_bfloat16* Ahs = base;
        const __nv_bfloat16* Als = base + TILE_ELEMS;
        const __nv_bfloat16* Bhs = base + 2 * TILE_ELEMS;
        const __nv_bfloat16* Bls = base + 3 * TILE_ELEMS;

#pragma unroll
        for (int ks = 0; ks < 2; ks++) {
            const int koff = ks * 16 + (lane & 3) * 2;
            const int nrow = wn * 32 + (lane >> 2);
            uint32_t bh0[4], bh1[4], bl0[4], bl1[4];
#pragma unroll
            for (int ni = 0; ni < 4; ni++) {
                int n = nrow + ni * 8;
                bh0[ni] = *(const uint32_t*)(Bhs + n * PB + koff);
                bh1[ni] = *(const uint32_t*)(Bhs + n * PB + koff + 8);
                bl0[ni] = *(const uint32_t*)(Bls + n * PB + koff);
                bl1[ni] = *(const uint32_t*)(Bls + n * PB + koff + 8);
            }
            const int arow = wm * 64 + (lane >> 2);
#pragma unroll
            for (int mi = 0; mi < 4; mi++) {
                int r = arow + mi * 16;
                uint32_t ah0 = *(const uint32_t*)(Ahs + r * PB + koff);
                uint32_t ah1 = *(const uint32_t*)(Ahs + (r + 8) * PB + koff);
                uint32_t ah2 = *(const uint32_t*)(Ahs + r * PB + koff + 8);
                uint32_t ah3 = *(const uint32_t*)(Ahs + (r + 8) * PB + koff + 8);
                uint32_t al0 = *(const uint32_t*)(Als + r * PB + koff);
                uint32_t al1 = *(const uint32_t*)(Als + (r + 8) * PB + koff);
                uint32_t al2 = *(const uint32_t*)(Als + r * PB + koff + 8);
                uint32_t al3 = *(const uint32_t*)(Als + (r + 8) * PB + koff + 8);
                // product-major: same-acc dependency distance = 4 MMAs
#pragma unroll
                for (int ni = 0; ni < 4; ni++)
                    mma_bf16(acc[mi][ni], ah0, ah1, ah2, ah3, bh0[ni], bh1[ni]);
#pragma unroll
                for (int ni = 0; ni < 4; ni++)
                    mma_bf16(acc[mi][ni], ah0, ah1, ah2, ah3, bl0[ni], bl1[ni]);
#pragma unroll
                for (int ni = 0; ni < 4; ni++)
                    mma_bf16(acc[mi][ni], al0, al1, al2, al3, bh0[ni], bh1[ni]);
            }
        }
        __syncthreads();
    }

#pragma unroll
    for (int mi = 0; mi < 4; mi++) {
        int r0 = rowM + wm * 64 + mi * 16 + (lane >> 2);
#pragma unroll
        for (int ni = 0; ni < 4; ni++) {
            int c0 = rowN + wn * 32 + ni * 8 + (lane & 3) * 2;
            float bv0 = bias[c0], bv1 = bias[c0 + 1];
            float v00 = acc[mi][ni][0] + bv0, v01 = acc[mi][ni][1] + bv1;
            float v10 = acc[mi][ni][2] + bv0, v11 = acc[mi][ni][3] + bv1;
            if (MODE == 0) {
                int part = c0 >> 10, hh = (c0 >> 6) & 15, l = c0 & 63;
#pragma unroll
                for (int rr = 0; rr < 2; rr++) {
                    int m = r0 + rr * 8;
                    int bb = m >> 11, n = m & (SEQ - 1);
                    size_t dst = ((size_t)(bb * NH + hh) * SEQ + n) * HD + l;
                    float x0 = rr ? v10 : v00, x1 = rr ? v11 : v01;
                    uint32_t hi, lo;
                    if (part == 0) {
                        split2(x0 * 0.125f, x1 * 0.125f, hi, lo);
                        *(uint32_t*)&g_Qh[dst] = hi; *(uint32_t*)&g_Ql[dst] = lo;
                    } else if (part == 1) {
                        split2(x0, x1, hi, lo);
                        *(uint32_t*)&g_Kh[dst] = hi; *(uint32_t*)&g_Kl[dst] = lo;
                    } else {
                        split2(x0, x1, hi, lo);
                        *(uint32_t*)&g_Vh[dst] = hi; *(uint32_t*)&g_Vl[dst] = lo;
                    }
                }
            } else {
                *(float2*)&C[(size_t)r0 * HID + c0]       = make_float2(v00, v01);
                *(float2*)&C[(size_t)(r0 + 8) * HID + c0] = make_float2(v10, v11);
            }
        }
    }
}

// ---------------------------------------------------------------------------
// HMMA causal flash attention; epilogue emits split bf16 AO directly.
// ---------------------------------------------------------------------------
__global__ __launch_bounds__(256, 1) void attn_mma(__nv_bfloat16* __restrict__ AOh,
                                                   __nv_bfloat16* __restrict__ AOl)
{
    __shared__ __nv_bfloat16 Ksh[64*72], Ksl[64*72], Vsh[64*72], Vsl[64*72];
    const int tid = threadIdx.x, lane = tid & 31, warp = tid >> 5;
    const int qt = (int)(gridDim.x - 1 - blockIdx.x);   // heavy tiles first
    const int hh = blockIdx.y, bb = blockIdx.z;
    const int bh = bb * NH + hh;
    const int qbase = qt * 128;
    const int rq = lane >> 2, cq = (lane & 3) * 2;
    const int row0 = qbase + warp * 16 + rq;
    const int lt = lane >> 3, lr = lane & 7;

    uint32_t qh[4][4], ql[4][4];
    {
        const uint32_t* Qh32 = (const uint32_t*)g_Qh + (size_t)bh * SEQ * HD / 2;
        const uint32_t* Ql32 = (const uint32_t*)g_Ql + (size_t)bh * SEQ * HD / 2;
        int r0 = row0, r1 = row0 + 8;
#pragma unroll
        for (int ks = 0; ks < 4; ks++) {
            int d0 = ks * 16 + cq;
            qh[ks][0] = Qh32[(r0 * HD + d0) >> 1];
            qh[ks][1] = Qh32[(r1 * HD + d0) >> 1];
            qh[ks][2] = Qh32[(r0 * HD + d0 + 8) >> 1];
            qh[ks][3] = Qh32[(r1 * HD + d0 + 8) >> 1];
            ql[ks][0] = Ql32[(r0 * HD + d0) >> 1];
            ql[ks][1] = Ql32[(r1 * HD + d0) >> 1];
            ql[ks][2] = Ql32[(r0 * HD + d0 + 8) >> 1];
            ql[ks][3] = Ql32[(r1 * HD + d0 + 8) >> 1];
        }
    }

    float o[8][4];
#pragma unroll
    for (int i = 0; i < 8; i++)
#pragma unroll
        for (int j = 0; j < 4; j++) o[i][j] = 0.0f;
    float m2[2] = {-1e30f, -1e30f}, l2[2] = {0.0f, 0.0f};

    const uint32_t sKh = smem_u32(Ksh), sKl = smem_u32(Ksl);
    const uint32_t sVh = smem_u32(Vsh), sVl = smem_u32(Vsl);
    const uint32_t kOff = (uint32_t)(((lr + ((lt >> 1) << 3)) * 72 + ((lt & 1) << 3)) * 2);
    const uint32_t vOff = (uint32_t)(((lr + ((lt & 1) << 3)) * 72 + ((lt >> 1) << 3)) * 2);

    const int NKT = 2 * qt + 2;
    for (int kt = 0; kt < NKT; kt++) {
        {   // stage K/V hi/lo tiles (64x64), row-major, pitch 72
            size_t gb = (size_t)(bh * SEQ + kt * 64) * HD;
            const uint4* s0 = (const uint4*)(g_Kh + gb);
            const uint4* s1 = (const uint4*)(g_Kl + gb);
            const uint4* s2 = (const uint4*)(g_Vh + gb);
            const uint4* s3 = (const uint4*)(g_Vl + gb);
#pragma unroll
            for (int t = 0; t < 2; t++) {
                int idx = t * 256 + tid;
                int r = idx >> 3, c = idx & 7;
                *(uint4*)&Ksh[r * 72 + c * 8] = s0[r * 8 + c];
                *(uint4*)&Ksl[r * 72 + c * 8] = s1[r * 8 + c];
                *(uint4*)&Vsh[r * 72 + c * 8] = s2[r * 8 + c];
                *(uint4*)&Vsl[r * 72 + c * 8] = s3[r * 8 + c];
            }
        }
        __syncthreads();

        // ---- S = Q.K^T (3-product, interleaved pairs) ----
        float s[8][4];
#pragma unroll
        for (int i = 0; i < 8; i++)
#pragma unroll
            for (int j = 0; j < 4; j++) s[i][j] = 0.0f;
#pragma unroll
        for (int ks = 0; ks < 4; ks++) {
#pragma unroll
            for (int p = 0; p < 4; p++) {
                uint32_t off = (uint32_t)((p * 16 * 72 + ks * 16) * 2);
                uint32_t kh0, kh1, kh2, kh3, kl0, kl1, kl2, kl3;
                LDM4(kh0, kh1, kh2, kh3, sKh + kOff + off);
                LDM4(kl0, kl1, kl2, kl3, sKl + kOff + off);
                mma_bf16(s[2*p],   qh[ks][0], qh[ks][1], qh[ks][2], qh[ks][3], kh0, kh1);
                mma_bf16(s[2*p+1], qh[ks][0], qh[ks][1], qh[ks][2], qh[ks][3], kh2, kh3);
                mma_bf16(s[2*p],   qh[ks][0], qh[ks][1], qh[ks][2], qh[ks][3], kl0, kl1);
                mma_bf16(s[2*p+1], qh[ks][0], qh[ks][1], qh[ks][2], qh[ks][3], kl2, kl3);
                mma_bf16(s[2*p],   ql[ks][0], ql[ks][1], ql[ks][2], ql[ks][3], kh0, kh1);
                mma_bf16(s[2*p+1], ql[ks][0], ql[ks][1], ql[ks][2], ql[ks][3], kh2, kh3);
            }
        }

        // ---- causal mask ----
        if (kt >= 2 * qt) {
            int kb = kt * 64;
#pragma unroll
            for (int ni = 0; ni < 8; ni++)
#pragma unroll
                for (int c = 0; c < 4; c++) {
                    int key = kb + ni * 8 + cq + (c & 1);
                    int qr  = row0 + ((c >> 1) << 3);
                    if (key > qr) s[ni][c] = -1e30f;
                }
        }

        // ---- online softmax in accumulator layout ----
#pragma unroll
        for (int half = 0; half < 2; half++) {
            float mx = -1e30f;
#pragma unroll
            for (int ni = 0; ni < 8; ni++)
                mx = fmaxf(mx, fmaxf(s[ni][half*2], s[ni][half*2+1]));
            mx = fmaxf(mx, __shfl_xor_sync(0xffffffffu, mx, 1));
            mx = fmaxf(mx, __shfl_xor_sync(0xffffffffu, mx, 2));
            float mn = fmaxf(m2[half], mx);
            float alpha = __expf(m2[half] - mn);
            float sum = 0.0f;
#pragma unroll
            for (int ni = 0; ni < 8; ni++) {
                float e0 = __expf(s[ni][half*2]   - mn);
                float e1 = __expf(s[ni][half*2+1] - mn);
                s[ni][half*2] = e0; s[ni][half*2+1] = e1;
                sum += e0 + e1;
            }
            sum += __shfl_xor_sync(0xffffffffu, sum, 1);
            sum += __shfl_xor_sync(0xffffffffu, sum, 2);
            l2[half] = l2[half] * alpha + sum;
            m2[half] = mn;
#pragma unroll
            for (int dn = 0; dn < 8; dn++) {
                o[dn][half*2]   *= alpha;
                o[dn][half*2+1] *= alpha;
            }
        }

        // ---- repack P (accumulator -> A fragments), split hi/lo ----
        uint32_t ph[4][4], pl[4][4];
#pragma unroll
        for (int k2 = 0; k2 < 4; k2++) {
            int n0 = 2 * k2, n1 = n0 + 1;
            split2(s[n0][0], s[n0][1], ph[k2][0], pl[k2][0]);
            split2(s[n0][2], s[n0][3], ph[k2][1], pl[k2][1]);
            split2(s[n1][0], s[n1][1], ph[k2][2], pl[k2][2]);
            split2(s[n1][2], s[n1][3], ph[k2][3], pl[k2][3]);
        }

        // ---- O += P.V (3-product, interleaved pairs) ----
#pragma unroll
        for (int k2 = 0; k2 < 4; k2++) {
#pragma unroll
            for (int p = 0; p < 4; p++) {
                uint32_t off = (uint32_t)((k2 * 16 * 72 + p * 16) * 2);
                uint32_t vh0, vh1, vh2, vh3, vl0, vl1, vl2, vl3;
                LDM4T(vh0, vh1, vh2, vh3, sVh + vOff + off);
                LDM4T(vl0, vl1, vl2, vl3, sVl + vOff + off);
                mma_bf16(o[2*p],   ph[k2][0], ph[k2][1], ph[k2][2], ph[k2][3], vh0, vh1);
                mma_bf16(o[2*p+1], ph[k2][0], ph[k2][1], ph[k2][2], ph[k2][3], vh2, vh3);
                mma_bf16(o[2*p],   ph[k2][0], ph[k2][1], ph[k2][2], ph[k2][3], vl0, vl1);
                mma_bf16(o[2*p+1], ph[k2][0], ph[k2][1], ph[k2][2], ph[k2][3], vl2, vl3);
                mma_bf16(o[2*p],   pl[k2][0], pl[k2][1], pl[k2][2], pl[k2][3], vh0, vh1);
                mma_bf16(o[2*p+1], pl[k2][0], pl[k2][1], pl[k2][2], pl[k2][3], vh2, vh3);
            }
        }
        __syncthreads();
    }

    // ---- normalize + split + write AO hi/lo [b, n, h*64+d] ----
#pragma unroll
    for (int half = 0; half < 2; half++) {
        float inv = 1.0f / l2[half];
        int row = row0 + half * 8;
        size_t base = ((size_t)(bb * SEQ + row)) * HID + hh * HD;
#pragma unroll
        for (int dn = 0; dn < 8; dn++) {
            uint32_t hi, lo;
            split2(o[dn][half*2] * inv, o[dn][half*2+1] * inv, hi, lo);
            *(uint32_t*)&AOh[base + dn * 8 + cq] = hi;
            *(uint32_t*)&AOl[base + dn * 8 + cq] = lo;
        }
    }
}

// ---------------------------------------------------------------------------
extern "C" void kernel_launch(void* const* d_in, const int* in_sizes, int n_in,
                              void* d_out, int out_size)
{
    const float* enc    = (const float*)d_in[0];
    const float* W_attn = (const float*)d_in[1];
    const float* b_attn = (const float*)d_in[2];
    const float* W_out  = (const float*)d_in[3];
    const float* b_out  = (const float*)d_in[4];
    float* out = (float*)d_out;

    __nv_bfloat16 *d_Ah, *d_Al, *d_WqTh, *d_WqTl, *d_WoTh, *d_WoTl, *d_AOh, *d_AOl;
    cudaGetSymbolAddress((void**)&d_Ah,   g_Ah);
    cudaGetSymbolAddress((void**)&d_Al,   g_Al);
    cudaGetSymbolAddress((void**)&d_WqTh, g_WqTh);
    cudaGetSymbolAddress((void**)&d_WqTl, g_WqTl);
    cudaGetSymbolAddress((void**)&d_WoTh, g_WoTh);
    cudaGetSymbolAddress((void**)&d_WoTl, g_WoTl);
    cudaGetSymbolAddress((void**)&d_AOh,  g_AOh);
    cudaGetSymbolAddress((void**)&d_AOl,  g_AOl);

    const size_t gsmem = (size_t)2 * BUF_ELEMS * sizeof(__nv_bfloat16);  // 81920 B
    cudaFuncSetAttribute(gemm_mma<0>, cudaFuncAttributeMaxDynamicSharedMemorySize, (int)gsmem);
    cudaFuncSetAttribute(gemm_mma<1>, cudaFuncAttributeMaxDynamicSharedMemorySize, (int)gsmem);

    // 0) prep: split enc, transpose+split weights
    split_kernel<<<(MTOK*HID/4 + 255)/256, 256>>>((const float4*)enc, d_Ah, d_Al, MTOK*HID/4);
    transpose_split<<<dim3(3*HID/32, HID/32), dim3(32,8)>>>(W_attn, d_WqTh, d_WqTl, HID, 3*HID);
    transpose_split<<<dim3(HID/32, HID/32),   dim3(32,8)>>>(W_out,  d_WoTh, d_WoTl, HID, HID);

    // 1) QKV projection (HMMA) -> split bf16 head-major Q/K/V
    gemm_mma<0><<<dim3(3*HID/128, MTOK/128), 256, gsmem>>>(d_Ah, d_Al, d_WqTh, d_WqTl,
                                                           b_attn, nullptr);

    // 2) causal attention (HMMA) -> split bf16 AO directly
    attn_mma<<<dim3(SEQ/128, NH, BATCH), 256>>>(d_AOh, d_AOl);

    // 3) output projection (HMMA)
    gemm_mma<1><<<dim3(HID/128, MTOK/128), 256, gsmem>>>(d_AOh, d_AOl, d_WoTh, d_WoTl,
                                                         b_out, out);
}

// round 17
// speedup vs baseline: 2.5469x; 1.0878x over previous
#include <cuda_runtime.h>
#include <cuda_bf16.h>
#include <stdint.h>
#include <math.h>

#define SEQ   2048
#define BATCH 2
#define HID   1024
#define NH    16
#define HD    64
#define MTOK  (BATCH*SEQ)   // 4096

// ---------------- scratch (allocation-free) ----------------
__device__ __nv_bfloat16 g_Ah[MTOK*HID],    g_Al[MTOK*HID];      // enc split
__device__ __nv_bfloat16 g_WqTh[3*HID*HID], g_WqTl[3*HID*HID];   // W_attn^T split
__device__ __nv_bfloat16 g_WoTh[HID*HID],   g_WoTl[HID*HID];     // W_out^T split
__device__ __nv_bfloat16 g_AOh[MTOK*HID],   g_AOl[MTOK*HID];     // attn out split
// head-major bf16 split Q/K/V ([bh][n][d]); Q pre-scaled by 1/8
__device__ __nv_bfloat16 g_Qh[BATCH*NH*SEQ*HD], g_Ql[BATCH*NH*SEQ*HD];
__device__ __nv_bfloat16 g_Kh[BATCH*NH*SEQ*HD], g_Kl[BATCH*NH*SEQ*HD];
__device__ __nv_bfloat16 g_Vh[BATCH*NH*SEQ*HD], g_Vl[BATCH*NH*SEQ*HD];

__device__ __forceinline__ uint32_t smem_u32(const void* p) {
    uint32_t a;
    asm("{ .reg .u64 t; cvta.to.shared.u64 t, %1; cvt.u32.u64 %0, t; }" : "=r"(a) : "l"(p));
    return a;
}

__device__ __forceinline__ void mma_bf16(float* d,
                                         uint32_t a0, uint32_t a1, uint32_t a2, uint32_t a3,
                                         uint32_t b0, uint32_t b1) {
    asm volatile("mma.sync.aligned.m16n8k16.row.col.f32.bf16.bf16.f32 "
                 "{%0,%1,%2,%3}, {%4,%5,%6,%7}, {%8,%9}, {%0,%1,%2,%3};"
                 : "+f"(d[0]), "+f"(d[1]), "+f"(d[2]), "+f"(d[3])
                 : "r"(a0), "r"(a1), "r"(a2), "r"(a3), "r"(b0), "r"(b1));
}

#define LDM4(r0,r1,r2,r3, a) \
    asm volatile("ldmatrix.sync.aligned.m8n8.x4.shared.b16 {%0,%1,%2,%3}, [%4];" \
        : "=r"(r0),"=r"(r1),"=r"(r2),"=r"(r3) : "r"(a))
#define LDM4T(r0,r1,r2,r3, a) \
    asm volatile("ldmatrix.sync.aligned.m8n8.x4.trans.shared.b16 {%0,%1,%2,%3}, [%4];" \
        : "=r"(r0),"=r"(r1),"=r"(r2),"=r"(r3) : "r"(a))

// split fp32 pair -> hi/lo bf16x2
__device__ __forceinline__ void split2(float x, float y, uint32_t& hi, uint32_t& lo) {
    __nv_bfloat162 t = __floats2bfloat162_rn(x, y);
    hi = *(uint32_t*)&t;
    float xr = x - __bfloat162float(t.x);
    float yr = y - __bfloat162float(t.y);
    __nv_bfloat162 u = __floats2bfloat162_rn(xr, yr);
    lo = *(uint32_t*)&u;
}

// ---------------- split / transpose-split ----------------
__global__ void split_kernel(const float4* __restrict__ src,
                             __nv_bfloat16* __restrict__ h,
                             __nv_bfloat16* __restrict__ l, int n4)
{
    int i = blockIdx.x * blockDim.x + threadIdx.x;
    if (i >= n4) return;
    float4 v = src[i];
    float a[4] = {v.x, v.y, v.z, v.w};
#pragma unroll
    for (int j = 0; j < 4; j++) {
        __nv_bfloat16 hi = __float2bfloat16(a[j]);
        h[4*i + j] = hi;
        l[4*i + j] = __float2bfloat16(a[j] - __bfloat162float(hi));
    }
}

__global__ void transpose_split(const float* __restrict__ W,
                                __nv_bfloat16* __restrict__ Th,
                                __nv_bfloat16* __restrict__ Tl, int K, int N)
{
    __shared__ float t[32][33];
    int bn = blockIdx.x * 32, bk = blockIdx.y * 32;
    int tx = threadIdx.x, ty = threadIdx.y;
#pragma unroll
    for (int j = 0; j < 32; j += 8)
        t[ty + j][tx] = W[(size_t)(bk + ty + j) * N + bn + tx];
    __syncthreads();
#pragma unroll
    for (int j = 0; j < 32; j += 8) {
        float v = t[tx][ty + j];
        __nv_bfloat16 hi = __float2bfloat16(v);
        size_t o = (size_t)(bn + ty + j) * K + bk + tx;
        Th[o] = hi;
        Tl[o] = __float2bfloat16(v - __bfloat162float(hi));
    }
}

// ---------------------------------------------------------------------------
// Split-bf16 HMMA GEMM: C[4096, N] = A @ B^T + bias  (hh+hl+lh)
// ldmatrix.x4 fragment loads (4x fewer smem instructions than scalar LDS).
// MODE 0: qkv epilogue -> bf16 split head-major Q(*0.125)/K/V. MODE 1: fp32 C.
// ---------------------------------------------------------------------------
#define PB 40
#define TILE_ELEMS (128*PB)
#define BUF_ELEMS  (4*TILE_ELEMS)

template<int MODE>
__global__ __launch_bounds__(256, 2) void gemm_mma(
    const __nv_bfloat16* __restrict__ Ah, const __nv_bfloat16* __restrict__ Al,
    const __nv_bfloat16* __restrict__ Bh, const __nv_bfloat16* __restrict__ Bl,
    const float* __restrict__ bias, float* __restrict__ C)
{
    extern __shared__ __nv_bfloat16 sm[];
    const int tid = threadIdx.x, lane = tid & 31, warp = tid >> 5;
    const int wm = warp >> 2, wn = warp & 3;
    const int rowM = blockIdx.y * 128, rowN = blockIdx.x * 128;
    const uint32_t sbase = smem_u32(sm);
    const int lt = lane >> 3, lr = lane & 7;

    // ldmatrix per-lane offsets (bytes within a tile)
    //  A operand: lt&1 -> row+8, lt>>1 -> col+8
    const uint32_t aOff = (uint32_t)(((lr + ((lt & 1) << 3)) * PB + ((lt >> 1) << 3)) * 2);
    //  B operand: lt>>1 -> n+8, lt&1 -> k+8
    const uint32_t bOff = (uint32_t)(((lr + ((lt >> 1) << 3)) * PB + ((lt & 1) << 3)) * 2);

    float acc[4][4][4];
#pragma unroll
    for (int a = 0; a < 4; a++)
#pragma unroll
        for (int b = 0; b < 4; b++)
#pragma unroll
            for (int c = 0; c < 4; c++) acc[a][b][c] = 0.0f;

    const __nv_bfloat16* gsrc[4] = {Ah, Al, Bh, Bl};
    const int rb[4] = {rowM, rowM, rowN, rowN};

    auto issue = [&](int ch, int buf) {
#pragma unroll
        for (int t4 = 0; t4 < 4; t4++) {
#pragma unroll
            for (int t = 0; t < 2; t++) {
                int idx = t * 256 + tid;
                int r = idx >> 2, cqk = idx & 3;
                const __nv_bfloat16* g = gsrc[t4] + (size_t)(rb[t4] + r) * HID + ch * 32 + cqk * 8;
                uint32_t s = sbase + (uint32_t)(buf * BUF_ELEMS + t4 * TILE_ELEMS) * 2u
                                   + (uint32_t)(r * (PB * 2) + cqk * 16);
                asm volatile("cp.async.cg.shared.global [%0], [%1], 16;\n" :: "r"(s), "l"(g));
            }
        }
        asm volatile("cp.async.commit_group;\n" ::: "memory");
    };

    issue(0, 0);

    const int NC = HID / 32;
    for (int ch = 0; ch < NC; ch++) {
        if (ch + 1 < NC) {
            issue(ch + 1, (ch + 1) & 1);
            asm volatile("cp.async.wait_group 1;\n" ::: "memory");
        } else {
            asm volatile("cp.async.wait_group 0;\n" ::: "memory");
        }
        __syncthreads();

        const uint32_t base = sbase + (uint32_t)((ch & 1) * BUF_ELEMS) * 2u;
        const uint32_t sAh = base;
        const uint32_t sAl = base + TILE_ELEMS * 2u;
        const uint32_t sBh = base + 2u * TILE_ELEMS * 2u;
        const uint32_t sBl = base + 3u * TILE_ELEMS * 2u;

#pragma unroll
        for (int ks = 0; ks < 2; ks++) {
            const uint32_t kByte = (uint32_t)(ks * 16 * 2);
            // B fragments for 32 n: 2 LDM4 hi + 2 LDM4 lo
            uint32_t bh[8], bl[8];
#pragma unroll
            for (int h2 = 0; h2 < 2; h2++) {
                uint32_t nByte = (uint32_t)((wn * 32 + h2 * 16) * PB * 2);
                LDM4(bh[h2*4+0], bh[h2*4+1], bh[h2*4+2], bh[h2*4+3],
                     sBh + nByte + kByte + bOff);
                LDM4(bl[h2*4+0], bl[h2*4+1], bl[h2*4+2], bl[h2*4+3],
                     sBl + nByte + kByte + bOff);
            }
#pragma unroll
            for (int mi = 0; mi < 4; mi++) {
                uint32_t mByte = (uint32_t)((wm * 64 + mi * 16) * PB * 2);
                uint32_t ah0, ah1, ah2, ah3, al0, al1, al2, al3;
                LDM4(ah0, ah1, ah2, ah3, sAh + mByte + kByte + aOff);
                LDM4(al0, al1, al2, al3, sAl + mByte + kByte + aOff);
                // product-major: same-acc dependency distance = 4 MMAs
#pragma unroll
                for (int ni = 0; ni < 4; ni++)
                    mma_bf16(acc[mi][ni], ah0, ah1, ah2, ah3, bh[ni*2], bh[ni*2+1]);
#pragma unroll
                for (int ni = 0; ni < 4; ni++)
                    mma_bf16(acc[mi][ni], ah0, ah1, ah2, ah3, bl[ni*2], bl[ni*2+1]);
#pragma unroll
                for (int ni = 0; ni < 4; ni++)
                    mma_bf16(acc[mi][ni], al0, al1, al2, al3, bh[ni*2], bh[ni*2+1]);
            }
        }
        __syncthreads();
    }

#pragma unroll
    for (int mi = 0; mi < 4; mi++) {
        int r0 = rowM + wm * 64 + mi * 16 + (lane >> 2);
#pragma unroll
        for (int ni = 0; ni < 4; ni++) {
            int c0 = rowN + wn * 32 + ni * 8 + (lane & 3) * 2;
            float bv0 = bias[c0], bv1 = bias[c0 + 1];
            float v00 = acc[mi][ni][0] + bv0, v01 = acc[mi][ni][1] + bv1;
            float v10 = acc[mi][ni][2] + bv0, v11 = acc[mi][ni][3] + bv1;
            if (MODE == 0) {
                int part = c0 >> 10, hh = (c0 >> 6) & 15, l = c0 & 63;
#pragma unroll
                for (int rr = 0; rr < 2; rr++) {
                    int m = r0 + rr * 8;
                    int bb = m >> 11, n = m & (SEQ - 1);
                    size_t dst = ((size_t)(bb * NH + hh) * SEQ + n) * HD + l;
                    float x0 = rr ? v10 : v00, x1 = rr ? v11 : v01;
                    uint32_t hi, lo;
                    if (part == 0) {
                        split2(x0 * 0.125f, x1 * 0.125f, hi, lo);
                        *(uint32_t*)&g_Qh[dst] = hi; *(uint32_t*)&g_Ql[dst] = lo;
                    } else if (part == 1) {
                        split2(x0, x1, hi, lo);
                        *(uint32_t*)&g_Kh[dst] = hi; *(uint32_t*)&g_Kl[dst] = lo;
                    } else {
                        split2(x0, x1, hi, lo);
                        *(uint32_t*)&g_Vh[dst] = hi; *(uint32_t*)&g_Vl[dst] = lo;
                    }
                }
            } else {
                *(float2*)&C[(size_t)r0 * HID + c0]       = make_float2(v00, v01);
                *(float2*)&C[(size_t)(r0 + 8) * HID + c0] = make_float2(v10, v11);
            }
        }
    }
}

// ---------------------------------------------------------------------------
// HMMA causal flash attention; epilogue emits split bf16 AO directly.
// ---------------------------------------------------------------------------
__global__ __launch_bounds__(256, 1) void attn_mma(__nv_bfloat16* __restrict__ AOh,
                                                   __nv_bfloat16* __restrict__ AOl)
{
    __shared__ __nv_bfloat16 Ksh[64*72], Ksl[64*72], Vsh[64*72], Vsl[64*72];
    const int tid = threadIdx.x, lane = tid & 31, warp = tid >> 5;
    const int qt = (int)(gridDim.x - 1 - blockIdx.x);   // heavy tiles first
    const int hh = blockIdx.y, bb = blockIdx.z;
    const int bh = bb * NH + hh;
    const int qbase = qt * 128;
    const int rq = lane >> 2, cq = (lane & 3) * 2;
    const int row0 = qbase + warp * 16 + rq;
    const int lt = lane >> 3, lr = lane & 7;

    uint32_t qh[4][4], ql[4][4];
    {
        const uint32_t* Qh32 = (const uint32_t*)g_Qh + (size_t)bh * SEQ * HD / 2;
        const uint32_t* Ql32 = (const uint32_t*)g_Ql + (size_t)bh * SEQ * HD / 2;
        int r0 = row0, r1 = row0 + 8;
#pragma unroll
        for (int ks = 0; ks < 4; ks++) {
            int d0 = ks * 16 + cq;
            qh[ks][0] = Qh32[(r0 * HD + d0) >> 1];
            qh[ks][1] = Qh32[(r1 * HD + d0) >> 1];
            qh[ks][2] = Qh32[(r0 * HD + d0 + 8) >> 1];
            qh[ks][3] = Qh32[(r1 * HD + d0 + 8) >> 1];
            ql[ks][0] = Ql32[(r0 * HD + d0) >> 1];
            ql[ks][1] = Ql32[(r1 * HD + d0) >> 1];
            ql[ks][2] = Ql32[(r0 * HD + d0 + 8) >> 1];
            ql[ks][3] = Ql32[(r1 * HD + d0 + 8) >> 1];
        }
    }

    float o[8][4];
#pragma unroll
    for (int i = 0; i < 8; i++)
#pragma unroll
        for (int j = 0; j < 4; j++) o[i][j] = 0.0f;
    float m2[2] = {-1e30f, -1e30f}, l2[2] = {0.0f, 0.0f};

    const uint32_t sKh = smem_u32(Ksh), sKl = smem_u32(Ksl);
    const uint32_t sVh = smem_u32(Vsh), sVl = smem_u32(Vsl);
    const uint32_t kOff = (uint32_t)(((lr + ((lt >> 1) << 3)) * 72 + ((lt & 1) << 3)) * 2);
    const uint32_t vOff = (uint32_t)(((lr + ((lt & 1) << 3)) * 72 + ((lt >> 1) << 3)) * 2);

    const int NKT = 2 * qt + 2;
    for (int kt = 0; kt < NKT; kt++) {
        {   // stage K/V hi/lo tiles (64x64), row-major, pitch 72
            size_t gb = (size_t)(bh * SEQ + kt * 64) * HD;
            const uint4* s0 = (const uint4*)(g_Kh + gb);
            const uint4* s1 = (const uint4*)(g_Kl + gb);
            const uint4* s2 = (const uint4*)(g_Vh + gb);
            const uint4* s3 = (const uint4*)(g_Vl + gb);
#pragma unroll
            for (int t = 0; t < 2; t++) {
                int idx = t * 256 + tid;
                int r = idx >> 3, c = idx & 7;
                *(uint4*)&Ksh[r * 72 + c * 8] = s0[r * 8 + c];
                *(uint4*)&Ksl[r * 72 + c * 8] = s1[r * 8 + c];
                *(uint4*)&Vsh[r * 72 + c * 8] = s2[r * 8 + c];
                *(uint4*)&Vsl[r * 72 + c * 8] = s3[r * 8 + c];
            }
        }
        __syncthreads();

        // ---- S = Q.K^T (3-product, interleaved pairs) ----
        float s[8][4];
#pragma unroll
        for (int i = 0; i < 8; i++)
#pragma unroll
            for (int j = 0; j < 4; j++) s[i][j] = 0.0f;
#pragma unroll
        for (int ks = 0; ks < 4; ks++) {
#pragma unroll
            for (int p = 0; p < 4; p++) {
                uint32_t off = (uint32_t)((p * 16 * 72 + ks * 16) * 2);
                uint32_t kh0, kh1, kh2, kh3, kl0, kl1, kl2, kl3;
                LDM4(kh0, kh1, kh2, kh3, sKh + kOff + off);
                LDM4(kl0, kl1, kl2, kl3, sKl + kOff + off);
                mma_bf16(s[2*p],   qh[ks][0], qh[ks][1], qh[ks][2], qh[ks][3], kh0, kh1);
                mma_bf16(s[2*p+1], qh[ks][0], qh[ks][1], qh[ks][2], qh[ks][3], kh2, kh3);
                mma_bf16(s[2*p],   qh[ks][0], qh[ks][1], qh[ks][2], qh[ks][3], kl0, kl1);
                mma_bf16(s[2*p+1], qh[ks][0], qh[ks][1], qh[ks][2], qh[ks][3], kl2, kl3);
                mma_bf16(s[2*p],   ql[ks][0], ql[ks][1], ql[ks][2], ql[ks][3], kh0, kh1);
                mma_bf16(s[2*p+1], ql[ks][0], ql[ks][1], ql[ks][2], ql[ks][3], kh2, kh3);
            }
        }

        // ---- causal mask ----
        if (kt >= 2 * qt) {
            int kb = kt * 64;
#pragma unroll
            for (int ni = 0; ni < 8; ni++)
#pragma unroll
                for (int c = 0; c < 4; c++) {
                    int key = kb + ni * 8 + cq + (c & 1);
                    int qr  = row0 + ((c >> 1) << 3);
                    if (key > qr) s[ni][c] = -1e30f;
                }
        }

        // ---- online softmax in accumulator layout ----
#pragma unroll
        for (int half = 0; half < 2; half++) {
            float mx = -1e30f;
#pragma unroll
            for (int ni = 0; ni < 8; ni++)
                mx = fmaxf(mx, fmaxf(s[ni][half*2], s[ni][half*2+1]));
            mx = fmaxf(mx, __shfl_xor_sync(0xffffffffu, mx, 1));
            mx = fmaxf(mx, __shfl_xor_sync(0xffffffffu, mx, 2));
            float mn = fmaxf(m2[half], mx);
            float alpha = __expf(m2[half] - mn);
            float sum = 0.0f;
#pragma unroll
            for (int ni = 0; ni < 8; ni++) {
                float e0 = __expf(s[ni][half*2]   - mn);
                float e1 = __expf(s[ni][half*2+1] - mn);
                s[ni][half*2] = e0; s[ni][half*2+1] = e1;
                sum += e0 + e1;
            }
            sum += __shfl_xor_sync(0xffffffffu, sum, 1);
            sum += __shfl_xor_sync(0xffffffffu, sum, 2);
            l2[half] = l2[half] * alpha + sum;
            m2[half] = mn;
#pragma unroll
            for (int dn = 0; dn < 8; dn++) {
                o[dn][half*2]   *= alpha;
                o[dn][half*2+1] *= alpha;
            }
        }

        // ---- repack P (accumulator -> A fragments), split hi/lo ----
        uint32_t ph[4][4], pl[4][4];
#pragma unroll
        for (int k2 = 0; k2 < 4; k2++) {
            int n0 = 2 * k2, n1 = n0 + 1;
            split2(s[n0][0], s[n0][1], ph[k2][0], pl[k2][0]);
            split2(s[n0][2], s[n0][3], ph[k2][1], pl[k2][1]);
            split2(s[n1][0], s[n1][1], ph[k2][2], pl[k2][2]);
            split2(s[n1][2], s[n1][3], ph[k2][3], pl[k2][3]);
        }

        // ---- O += P.V (3-product, interleaved pairs) ----
#pragma unroll
        for (int k2 = 0; k2 < 4; k2++) {
#pragma unroll
            for (int p = 0; p < 4; p++) {
                uint32_t off = (uint32_t)((k2 * 16 * 72 + p * 16) * 2);
                uint32_t vh0, vh1, vh2, vh3, vl0, vl1, vl2, vl3;
                LDM4T(vh0, vh1, vh2, vh3, sVh + vOff + off);
                LDM4T(vl0, vl1, vl2, vl3, sVl + vOff + off);
                mma_bf16(o[2*p],   ph[k2][0], ph[k2][1], ph[k2][2], ph[k2][3], vh0, vh1);
                mma_bf16(o[2*p+1], ph[k2][0], ph[k2][1], ph[k2][2], ph[k2][3], vh2, vh3);
                mma_bf16(o[2*p],   ph[k2][0], ph[k2][1], ph[k2][2], ph[k2][3], vl0, vl1);
                mma_bf16(o[2*p+1], ph[k2][0], ph[k2][1], ph[k2][2], ph[k2][3], vl2, vl3);
                mma_bf16(o[2*p],   pl[k2][0], pl[k2][1], pl[k2][2], pl[k2][3], vh0, vh1);
                mma_bf16(o[2*p+1], pl[k2][0], pl[k2][1], pl[k2][2], pl[k2][3], vh2, vh3);
            }
        }
        __syncthreads();
    }

    // ---- normalize + split + write AO hi/lo [b, n, h*64+d] ----
#pragma unroll
    for (int half = 0; half < 2; half++) {
        float inv = 1.0f / l2[half];
        int row = row0 + half * 8;
        size_t base = ((size_t)(bb * SEQ + row)) * HID + hh * HD;
#pragma unroll
        for (int dn = 0; dn < 8; dn++) {
            uint32_t hi, lo;
            split2(o[dn][half*2] * inv, o[dn][half*2+1] * inv, hi, lo);
            *(uint32_t*)&AOh[base + dn * 8 + cq] = hi;
            *(uint32_t*)&AOl[base + dn * 8 + cq] = lo;
        }
    }
}

// ---------------------------------------------------------------------------
extern "C" void kernel_launch(void* const* d_in, const int* in_sizes, int n_in,
                              void* d_out, int out_size)
{
    const float* enc    = (const float*)d_in[0];
    const float* W_attn = (const float*)d_in[1];
    const float* b_attn = (const float*)d_in[2];
    const float* W_out  = (const float*)d_in[3];
    const float* b_out  = (const float*)d_in[4];
    float* out = (float*)d_out;

    __nv_bfloat16 *d_Ah, *d_Al, *d_WqTh, *d_WqTl, *d_WoTh, *d_WoTl, *d_AOh, *d_AOl;
    cudaGetSymbolAddress((void**)&d_Ah,   g_Ah);
    cudaGetSymbolAddress((void**)&d_Al,   g_Al);
    cudaGetSymbolAddress((void**)&d_WqTh, g_WqTh);
    cudaGetSymbolAddress((void**)&d_WqTl, g_WqTl);
    cudaGetSymbolAddress((void**)&d_WoTh, g_WoTh);
    cudaGetSymbolAddress((void**)&d_WoTl, g_WoTl);
    cudaGetSymbolAddress((void**)&d_AOh,  g_AOh);
    cudaGetSymbolAddress((void**)&d_AOl,  g_AOl);

    const size_t gsmem = (size_t)2 * BUF_ELEMS * sizeof(__nv_bfloat16);  // 81920 B
    cudaFuncSetAttribute(gemm_mma<0>, cudaFuncAttributeMaxDynamicSharedMemorySize, (int)gsmem);
    cudaFuncSetAttribute(gemm_mma<1>, cudaFuncAttributeMaxDynamicSharedMemorySize, (int)gsmem);

    // 0) prep: split enc, transpose+split weights
    split_kernel<<<(MTOK*HID/4 + 255)/256, 256>>>((const float4*)enc, d_Ah, d_Al, MTOK*HID/4);
    transpose_split<<<dim3(3*HID/32, HID/32), dim3(32,8)>>>(W_attn, d_WqTh, d_WqTl, HID, 3*HID);
    transpose_split<<<dim3(HID/32, HID/32),   dim3(32,8)>>>(W_out,  d_WoTh, d_WoTl, HID, HID);

    // 1) QKV projection (HMMA) -> split bf16 head-major Q/K/V
    gemm_mma<0><<<dim3(3*HID/128, MTOK/128), 256, gsmem>>>(d_Ah, d_Al, d_WqTh, d_WqTl,
                                                           b_attn, nullptr);

    // 2) causal attention (HMMA) -> split bf16 AO directly
    attn_mma<<<dim3(SEQ/128, NH, BATCH), 256>>>(d_AOh, d_AOl);

    // 3) output projection (HMMA)
    gemm_mma<1><<<dim3(HID/128, MTOK/128), 256, gsmem>>>(d_AOh, d_AOl, d_WoTh, d_WoTl,
                                                         b_out, out);
}